// round 1
// baseline (speedup 1.0000x reference)
#include <cuda_runtime.h>
#include <math.h>

#define NNODES 100000
#define NEDGES 3200000
#define NFEAT  256
#define NHID   128
#define NCLASS 40

// ---------------- scratch (static device globals; no allocs) ----------------
__device__ float g_s[(size_t)NNODES * NHID];   // self-projection
__device__ float g_z[(size_t)NNODES * NHID];   // neighbor-projection (pre-agg)
__device__ float g_h[(size_t)NNODES * NHID];   // layer output
__device__ int   g_deg[NNODES];
__device__ int   g_rowptr[NNODES + 1];
__device__ int   g_cursor[NNODES];
__device__ int   g_col[NEDGES];

// ---------------- CSR build ----------------
__global__ void k_zero_deg(int* __restrict__ deg) {
    int i = blockIdx.x * blockDim.x + threadIdx.x;
    if (i < NNODES) deg[i] = 0;
}

__global__ void k_count(const int* __restrict__ rows, int* __restrict__ deg) {
    int e = blockIdx.x * blockDim.x + threadIdx.x;
    if (e < NEDGES) atomicAdd(&deg[rows[e]], 1);
}

// single-block exclusive scan over deg -> rowptr (and cursor copy)
__global__ void k_scan(const int* __restrict__ deg, int* __restrict__ rp,
                       int* __restrict__ cur) {
    __shared__ int wsum[32];
    __shared__ int carry;
    int tid = threadIdx.x, lane = tid & 31, wid = tid >> 5;
    if (tid == 0) carry = 0;
    __syncthreads();
    for (int base = 0; base < NNODES; base += 1024) {
        int i = base + tid;
        int v = (i < NNODES) ? deg[i] : 0;
        int x = v;
        #pragma unroll
        for (int d = 1; d < 32; d <<= 1) {
            int y = __shfl_up_sync(0xffffffffu, x, d);
            if (lane >= d) x += y;
        }
        if (lane == 31) wsum[wid] = x;
        __syncthreads();
        if (wid == 0) {
            int s = wsum[lane];
            #pragma unroll
            for (int d = 1; d < 32; d <<= 1) {
                int y = __shfl_up_sync(0xffffffffu, s, d);
                if (lane >= d) s += y;
            }
            wsum[lane] = s;
        }
        __syncthreads();
        int off  = carry + (wid ? wsum[wid - 1] : 0);
        int excl = off + x - v;
        if (i < NNODES) { rp[i] = excl; cur[i] = excl; }
        int tot = wsum[31];
        __syncthreads();
        if (tid == 0) carry += tot;
        __syncthreads();
    }
    if (tid == 0) rp[NNODES] = carry;
}

__global__ void k_fill(const int* __restrict__ rows, const int* __restrict__ cols,
                       int* __restrict__ cur, int* __restrict__ col) {
    int e = blockIdx.x * blockDim.x + threadIdx.x;
    if (e < NEDGES) {
        int p = atomicAdd(&cur[rows[e]], 1);
        col[p] = cols[e];
    }
}

// ---------------- SGEMM: C[M,128] = A[M,K] @ W'[128,K]^T (W' row stride ldw) ----------------
__global__ __launch_bounds__(256) void k_sgemm(const float* __restrict__ A, int K,
                                               const float* __restrict__ W, int ldw,
                                               float* __restrict__ C) {
    const int BM = 128, BK = 8, TM = 8, TN = 8;
    __shared__ float As[BK][BM];
    __shared__ float Bs[BK][BM];
    int tid  = threadIdx.x;
    int row0 = blockIdx.x * BM;
    int lr   = tid >> 1;          // 0..127
    int lc   = (tid & 1) * 4;     // 0 or 4
    int tx   = tid & 15, ty = tid >> 4;

    float acc[TM][TN];
    #pragma unroll
    for (int i = 0; i < TM; i++)
        #pragma unroll
        for (int j = 0; j < TN; j++) acc[i][j] = 0.f;

    bool aok = (row0 + lr) < NNODES;
    const float* Aptr = A + (size_t)(row0 + lr) * K + lc;
    const float* Wptr = W + (size_t)lr * ldw + lc;

    for (int k0 = 0; k0 < K; k0 += BK) {
        float4 av = aok ? *(const float4*)(Aptr + k0) : make_float4(0.f, 0.f, 0.f, 0.f);
        float4 bv = *(const float4*)(Wptr + k0);
        As[lc + 0][lr] = av.x; As[lc + 1][lr] = av.y;
        As[lc + 2][lr] = av.z; As[lc + 3][lr] = av.w;
        Bs[lc + 0][lr] = bv.x; Bs[lc + 1][lr] = bv.y;
        Bs[lc + 2][lr] = bv.z; Bs[lc + 3][lr] = bv.w;
        __syncthreads();
        #pragma unroll
        for (int k = 0; k < BK; k++) {
            float af[TM], bf[TN];
            #pragma unroll
            for (int i = 0; i < TM; i++) af[i] = As[k][ty * TM + i];
            #pragma unroll
            for (int j = 0; j < TN; j++) bf[j] = Bs[k][tx * TN + j];
            #pragma unroll
            for (int i = 0; i < TM; i++)
                #pragma unroll
                for (int j = 0; j < TN; j++) acc[i][j] = fmaf(af[i], bf[j], acc[i][j]);
        }
        __syncthreads();
    }
    #pragma unroll
    for (int i = 0; i < TM; i++) {
        int gr = row0 + ty * TM + i;
        if (gr < NNODES) {
            float* cp = C + (size_t)gr * NHID + tx * TN;
            *(float4*)cp       = make_float4(acc[i][0], acc[i][1], acc[i][2], acc[i][3]);
            *(float4*)(cp + 4) = make_float4(acc[i][4], acc[i][5], acc[i][6], acc[i][7]);
        }
    }
}

// ---------------- SpMM + epilogue: h = relu(s + (A@z)/(deg+1)) ----------------
__global__ __launch_bounds__(256) void k_spmm(const float* __restrict__ z,
                                              const float* __restrict__ s,
                                              const int* __restrict__ rp,
                                              const int* __restrict__ col,
                                              const int* __restrict__ deg,
                                              float* __restrict__ h) {
    int lane = threadIdx.x & 31;
    int n    = (blockIdx.x * 256 + threadIdx.x) >> 5;
    if (n >= NNODES) return;
    int e = rp[n], end = rp[n + 1];
    float ax = 0.f, ay = 0.f, az = 0.f, aw = 0.f;
    for (; e + 2 <= end; e += 2) {
        int c0 = col[e], c1 = col[e + 1];
        float4 v0 = *(const float4*)(z + (size_t)c0 * NHID + lane * 4);
        float4 v1 = *(const float4*)(z + (size_t)c1 * NHID + lane * 4);
        ax += v0.x + v1.x; ay += v0.y + v1.y;
        az += v0.z + v1.z; aw += v0.w + v1.w;
    }
    if (e < end) {
        int c0 = col[e];
        float4 v0 = *(const float4*)(z + (size_t)c0 * NHID + lane * 4);
        ax += v0.x; ay += v0.y; az += v0.z; aw += v0.w;
    }
    float inv = 1.0f / (1.0f + (float)deg[n]);
    float4 sv = *(const float4*)(s + (size_t)n * NHID + lane * 4);
    float4 o;
    o.x = fmaxf(fmaf(ax, inv, sv.x), 0.f);
    o.y = fmaxf(fmaf(ay, inv, sv.y), 0.f);
    o.z = fmaxf(fmaf(az, inv, sv.z), 0.f);
    o.w = fmaxf(fmaf(aw, inv, sv.w), 0.f);
    *(float4*)(h + (size_t)n * NHID + lane * 4) = o;
}

// ---------------- MLP + log_softmax (warp per node) ----------------
__global__ __launch_bounds__(256) void k_mlp(const float* __restrict__ h,
                                             const float* __restrict__ Wm,
                                             const float* __restrict__ b,
                                             float* __restrict__ out) {
    __shared__ float4 Ws[NCLASS][NHID / 4];   // 40 x 32 float4
    __shared__ float  bs[NCLASS];
    int tid = threadIdx.x;
    for (int i = tid; i < NCLASS * (NHID / 4); i += 256)
        ((float4*)Ws)[i] = ((const float4*)Wm)[i];
    if (tid < NCLASS) bs[tid] = b[tid];
    __syncthreads();

    int lane = tid & 31;
    int n    = (blockIdx.x * 256 + tid) >> 5;
    if (n >= NNODES) return;

    float4 hv = *(const float4*)(h + (size_t)n * NHID + lane * 4);
    float l0 = 0.f, l1 = -INFINITY;
    #pragma unroll
    for (int c = 0; c < NCLASS; c++) {
        float4 w = Ws[c][lane];
        float p = hv.x * w.x + hv.y * w.y + hv.z * w.z + hv.w * w.w;
        #pragma unroll
        for (int d = 16; d >= 1; d >>= 1) p += __shfl_xor_sync(0xffffffffu, p, d);
        p += bs[c];
        if (c < 32) { if (lane == c)      l0 = p; }
        else        { if (lane == c - 32) l1 = p; }
    }
    float m = fmaxf(l0, l1);
    #pragma unroll
    for (int d = 16; d >= 1; d >>= 1) m = fmaxf(m, __shfl_xor_sync(0xffffffffu, m, d));
    float e = expf(l0 - m) + expf(l1 - m);
    #pragma unroll
    for (int d = 16; d >= 1; d >>= 1) e += __shfl_xor_sync(0xffffffffu, e, d);
    float lse = m + logf(e);
    out[(size_t)n * NCLASS + lane] = l0 - lse;
    if (lane < 8) out[(size_t)n * NCLASS + 32 + lane] = l1 - lse;
}

// ---------------- launch ----------------
extern "C" void kernel_launch(void* const* d_in, const int* in_sizes, int n_in,
                              void* d_out, int out_size) {
    const float* x    = (const float*)d_in[0];
    const float* W1   = (const float*)d_in[1];   // [128, 512]
    const float* W2   = (const float*)d_in[2];   // [128, 256]
    const float* mW   = (const float*)d_in[3];   // [40, 128]
    const float* mb   = (const float*)d_in[4];   // [40]
    const int*   rows = (const int*)d_in[5];
    const int*   cols = (const int*)d_in[6];
    float*       out  = (float*)d_out;

    float *p_s, *p_z, *p_h;
    int *p_deg, *p_rp, *p_cur, *p_col;
    cudaGetSymbolAddress((void**)&p_s,  g_s);
    cudaGetSymbolAddress((void**)&p_z,  g_z);
    cudaGetSymbolAddress((void**)&p_h,  g_h);
    cudaGetSymbolAddress((void**)&p_deg, g_deg);
    cudaGetSymbolAddress((void**)&p_rp,  g_rowptr);
    cudaGetSymbolAddress((void**)&p_cur, g_cursor);
    cudaGetSymbolAddress((void**)&p_col, g_col);

    const int GB_N = (NNODES + 255) / 256;
    const int GB_E = (NEDGES + 255) / 256;
    const int GB_W = (NNODES * 32 + 255) / 256;      // warp-per-node kernels
    const int GB_M = (NNODES + 127) / 128;           // gemm row tiles

    // CSR build (per replay; deterministic up to fp sum order)
    k_zero_deg<<<GB_N, 256>>>(p_deg);
    k_count<<<GB_E, 256>>>(rows, p_deg);
    k_scan<<<1, 1024>>>(p_deg, p_rp, p_cur);
    k_fill<<<GB_E, 256>>>(rows, cols, p_cur, p_col);

    // Layer 1: s = x@Wl1^T, z = x@Wr1^T, h = relu(s + (A@z)/(deg+1))
    k_sgemm<<<GB_M, 256>>>(x, NFEAT, W1,         2 * NFEAT, p_s);
    k_sgemm<<<GB_M, 256>>>(x, NFEAT, W1 + NFEAT, 2 * NFEAT, p_z);
    k_spmm<<<GB_W, 256>>>(p_z, p_s, p_rp, p_col, p_deg, p_h);

    // Layer 2
    k_sgemm<<<GB_M, 256>>>(p_h, NHID, W2,        2 * NHID, p_s);
    k_sgemm<<<GB_M, 256>>>(p_h, NHID, W2 + NHID, 2 * NHID, p_z);
    k_spmm<<<GB_W, 256>>>(p_z, p_s, p_rp, p_col, p_deg, p_h);

    // MLP + log_softmax
    k_mlp<<<GB_W, 256>>>(p_h, mW, mb, out);
}

// round 2
// speedup vs baseline: 1.3056x; 1.3056x over previous
#include <cuda_runtime.h>
#include <math.h>

#define NNODES 100000
#define NEDGES 3200000
#define NFEAT  256
#define NHID   128
#define NCLASS 40

// ---------------- scratch (static device globals; no allocs) ----------------
__device__ float g_s[(size_t)NNODES * NHID];   // self-projection
__device__ float g_z[(size_t)NNODES * NHID];   // neighbor-projection (pre-agg)
__device__ float g_h[(size_t)NNODES * NHID];   // layer output
__device__ int   g_deg[NNODES];
__device__ int   g_rowptr[NNODES + 1];
__device__ int   g_cursor[NNODES];
__device__ int   g_col[NEDGES];

// ---------------- CSR build ----------------
__global__ void k_zero_deg(int* __restrict__ deg) {
    int i = blockIdx.x * blockDim.x + threadIdx.x;
    if (i < NNODES) deg[i] = 0;
}

__global__ void k_count(const int* __restrict__ rows, int* __restrict__ deg) {
    int e = blockIdx.x * blockDim.x + threadIdx.x;
    if (e < NEDGES) atomicAdd(&deg[rows[e]], 1);
}

// single-block exclusive scan over deg -> rowptr (and cursor copy)
__global__ void k_scan(const int* __restrict__ deg, int* __restrict__ rp,
                       int* __restrict__ cur) {
    __shared__ int wsum[32];
    __shared__ int carry;
    int tid = threadIdx.x, lane = tid & 31, wid = tid >> 5;
    if (tid == 0) carry = 0;
    __syncthreads();
    for (int base = 0; base < NNODES; base += 1024) {
        int i = base + tid;
        int v = (i < NNODES) ? deg[i] : 0;
        int x = v;
        #pragma unroll
        for (int d = 1; d < 32; d <<= 1) {
            int y = __shfl_up_sync(0xffffffffu, x, d);
            if (lane >= d) x += y;
        }
        if (lane == 31) wsum[wid] = x;
        __syncthreads();
        if (wid == 0) {
            int s = wsum[lane];
            #pragma unroll
            for (int d = 1; d < 32; d <<= 1) {
                int y = __shfl_up_sync(0xffffffffu, s, d);
                if (lane >= d) s += y;
            }
            wsum[lane] = s;
        }
        __syncthreads();
        int off  = carry + (wid ? wsum[wid - 1] : 0);
        int excl = off + x - v;
        if (i < NNODES) { rp[i] = excl; cur[i] = excl; }
        int tot = wsum[31];
        __syncthreads();
        if (tid == 0) carry += tot;
        __syncthreads();
    }
    if (tid == 0) rp[NNODES] = carry;
}

__global__ void k_fill(const int* __restrict__ rows, const int* __restrict__ cols,
                       int* __restrict__ cur, int* __restrict__ col) {
    int e = blockIdx.x * blockDim.x + threadIdx.x;
    if (e < NEDGES) {
        int p = atomicAdd(&cur[rows[e]], 1);
        col[p] = cols[e];
    }
}

// ---------------- TF32 tensor-core GEMM ----------------
// C[M,128] = A[M,K] @ Whalf[128,K]^T, where W is [128, 2K] row-major and
// blockIdx.y selects the half (cols [0,K) -> C0, cols [K,2K) -> C1).
__device__ __forceinline__ unsigned f2tf32(float v) {
    unsigned u;
    asm("cvt.rna.tf32.f32 %0, %1;" : "=r"(u) : "f"(v));
    return u;
}

__device__ __forceinline__ void mma_tf32(float* c, const unsigned* a,
                                         unsigned b0, unsigned b1) {
    asm volatile(
        "mma.sync.aligned.m16n8k8.row.col.f32.tf32.tf32.f32 "
        "{%0,%1,%2,%3}, {%4,%5,%6,%7}, {%8,%9}, {%0,%1,%2,%3};"
        : "+f"(c[0]), "+f"(c[1]), "+f"(c[2]), "+f"(c[3])
        : "r"(a[0]), "r"(a[1]), "r"(a[2]), "r"(a[3]), "r"(b0), "r"(b1));
}

__global__ __launch_bounds__(256) void k_gemm_tf32(
    const float* __restrict__ A, int K,
    const float* __restrict__ W,
    float* __restrict__ C0, float* __restrict__ C1)
{
    __shared__ unsigned As[32][132];  // [k][m], padded
    __shared__ unsigned Bs[32][132];  // [k][n], padded
    const int tid = threadIdx.x, lane = tid & 31, wid = tid >> 5;
    const int warpM = wid & 3, warpN = wid >> 2;       // 4x2 warp grid
    const int row0 = blockIdx.x * 128;
    const int ldw = 2 * K;
    const float* Wb = W + (size_t)blockIdx.y * K;      // column offset in W row
    float* C = blockIdx.y ? C1 : C0;

    float acc[2][8][4];
    #pragma unroll
    for (int mi = 0; mi < 2; mi++)
        #pragma unroll
        for (int ni = 0; ni < 8; ni++)
            #pragma unroll
            for (int q = 0; q < 4; q++) acc[mi][ni][q] = 0.f;

    for (int k0 = 0; k0 < K; k0 += 32) {
        // load A tile: 128 rows x 32 cols -> As[k][m]
        #pragma unroll
        for (int j = 0; j < 4; j++) {
            int i  = tid + j * 256;
            int r  = i >> 3;
            int c4 = (i & 7) * 4;
            float4 v = make_float4(0.f, 0.f, 0.f, 0.f);
            if (row0 + r < NNODES)
                v = *(const float4*)(A + (size_t)(row0 + r) * K + k0 + c4);
            As[c4 + 0][r] = f2tf32(v.x); As[c4 + 1][r] = f2tf32(v.y);
            As[c4 + 2][r] = f2tf32(v.z); As[c4 + 3][r] = f2tf32(v.w);
        }
        // load B tile: 128 out-rows x 32 k-cols -> Bs[k][n]
        #pragma unroll
        for (int j = 0; j < 4; j++) {
            int i  = tid + j * 256;
            int n  = i >> 3;
            int c4 = (i & 7) * 4;
            float4 v = *(const float4*)(Wb + (size_t)n * ldw + k0 + c4);
            Bs[c4 + 0][n] = f2tf32(v.x); Bs[c4 + 1][n] = f2tf32(v.y);
            Bs[c4 + 2][n] = f2tf32(v.z); Bs[c4 + 3][n] = f2tf32(v.w);
        }
        __syncthreads();

        #pragma unroll
        for (int kk = 0; kk < 32; kk += 8) {
            unsigned af[2][4];
            const int kc = kk + (lane & 3);
            #pragma unroll
            for (int mi = 0; mi < 2; mi++) {
                int r = warpM * 32 + mi * 16 + (lane >> 2);
                af[mi][0] = As[kc][r];
                af[mi][1] = As[kc][r + 8];
                af[mi][2] = As[kc + 4][r];
                af[mi][3] = As[kc + 4][r + 8];
            }
            #pragma unroll
            for (int ni = 0; ni < 8; ni++) {
                int n = warpN * 64 + ni * 8 + (lane >> 2);
                unsigned b0 = Bs[kc][n];
                unsigned b1 = Bs[kc + 4][n];
                mma_tf32(acc[0][ni], af[0], b0, b1);
                mma_tf32(acc[1][ni], af[1], b0, b1);
            }
        }
        __syncthreads();
    }

    // writeback
    #pragma unroll
    for (int mi = 0; mi < 2; mi++) {
        int rbase = row0 + warpM * 32 + mi * 16 + (lane >> 2);
        #pragma unroll
        for (int ni = 0; ni < 8; ni++) {
            int col = warpN * 64 + ni * 8 + 2 * (lane & 3);
            if (rbase < NNODES)
                *(float2*)(C + (size_t)rbase * NHID + col) =
                    make_float2(acc[mi][ni][0], acc[mi][ni][1]);
            if (rbase + 8 < NNODES)
                *(float2*)(C + (size_t)(rbase + 8) * NHID + col) =
                    make_float2(acc[mi][ni][2], acc[mi][ni][3]);
        }
    }
}

// ---------------- SpMM + epilogue: h = relu(s + (A@z)/(deg+1)) ----------------
__global__ __launch_bounds__(256) void k_spmm(const float* __restrict__ z,
                                              const float* __restrict__ s,
                                              const int* __restrict__ rp,
                                              const int* __restrict__ col,
                                              const int* __restrict__ deg,
                                              float* __restrict__ h) {
    int lane = threadIdx.x & 31;
    int n    = (blockIdx.x * 256 + threadIdx.x) >> 5;
    if (n >= NNODES) return;
    int e = rp[n], end = rp[n + 1];
    float ax = 0.f, ay = 0.f, az = 0.f, aw = 0.f;
    for (; e + 2 <= end; e += 2) {
        int c0 = col[e], c1 = col[e + 1];
        float4 v0 = *(const float4*)(z + (size_t)c0 * NHID + lane * 4);
        float4 v1 = *(const float4*)(z + (size_t)c1 * NHID + lane * 4);
        ax += v0.x + v1.x; ay += v0.y + v1.y;
        az += v0.z + v1.z; aw += v0.w + v1.w;
    }
    if (e < end) {
        int c0 = col[e];
        float4 v0 = *(const float4*)(z + (size_t)c0 * NHID + lane * 4);
        ax += v0.x; ay += v0.y; az += v0.z; aw += v0.w;
    }
    float inv = 1.0f / (1.0f + (float)deg[n]);
    float4 sv = *(const float4*)(s + (size_t)n * NHID + lane * 4);
    float4 o;
    o.x = fmaxf(fmaf(ax, inv, sv.x), 0.f);
    o.y = fmaxf(fmaf(ay, inv, sv.y), 0.f);
    o.z = fmaxf(fmaf(az, inv, sv.z), 0.f);
    o.w = fmaxf(fmaf(aw, inv, sv.w), 0.f);
    *(float4*)(h + (size_t)n * NHID + lane * 4) = o;
}

// ---------------- MLP + log_softmax (warp per node) ----------------
__global__ __launch_bounds__(256) void k_mlp(const float* __restrict__ h,
                                             const float* __restrict__ Wm,
                                             const float* __restrict__ b,
                                             float* __restrict__ out) {
    __shared__ float4 Ws[NCLASS][NHID / 4];   // 40 x 32 float4
    __shared__ float  bs[NCLASS];
    int tid = threadIdx.x;
    for (int i = tid; i < NCLASS * (NHID / 4); i += 256)
        ((float4*)Ws)[i] = ((const float4*)Wm)[i];
    if (tid < NCLASS) bs[tid] = b[tid];
    __syncthreads();

    int lane = tid & 31;
    int n    = (blockIdx.x * 256 + tid) >> 5;
    if (n >= NNODES) return;

    float4 hv = *(const float4*)(h + (size_t)n * NHID + lane * 4);
    float l0 = 0.f, l1 = -INFINITY;
    #pragma unroll
    for (int c = 0; c < NCLASS; c++) {
        float4 w = Ws[c][lane];
        float p = hv.x * w.x + hv.y * w.y + hv.z * w.z + hv.w * w.w;
        #pragma unroll
        for (int d = 16; d >= 1; d >>= 1) p += __shfl_xor_sync(0xffffffffu, p, d);
        p += bs[c];
        if (c < 32) { if (lane == c)      l0 = p; }
        else        { if (lane == c - 32) l1 = p; }
    }
    float m = fmaxf(l0, l1);
    #pragma unroll
    for (int d = 16; d >= 1; d >>= 1) m = fmaxf(m, __shfl_xor_sync(0xffffffffu, m, d));
    float e = expf(l0 - m) + expf(l1 - m);
    #pragma unroll
    for (int d = 16; d >= 1; d >>= 1) e += __shfl_xor_sync(0xffffffffu, e, d);
    float lse = m + logf(e);
    out[(size_t)n * NCLASS + lane] = l0 - lse;
    if (lane < 8) out[(size_t)n * NCLASS + 32 + lane] = l1 - lse;
}

// ---------------- launch ----------------
extern "C" void kernel_launch(void* const* d_in, const int* in_sizes, int n_in,
                              void* d_out, int out_size) {
    const float* x    = (const float*)d_in[0];
    const float* W1   = (const float*)d_in[1];   // [128, 512]
    const float* W2   = (const float*)d_in[2];   // [128, 256]
    const float* mW   = (const float*)d_in[3];   // [40, 128]
    const float* mb   = (const float*)d_in[4];   // [40]
    const int*   rows = (const int*)d_in[5];
    const int*   cols = (const int*)d_in[6];
    float*       out  = (float*)d_out;

    float *p_s, *p_z, *p_h;
    int *p_deg, *p_rp, *p_cur, *p_col;
    cudaGetSymbolAddress((void**)&p_s,  g_s);
    cudaGetSymbolAddress((void**)&p_z,  g_z);
    cudaGetSymbolAddress((void**)&p_h,  g_h);
    cudaGetSymbolAddress((void**)&p_deg, g_deg);
    cudaGetSymbolAddress((void**)&p_rp,  g_rowptr);
    cudaGetSymbolAddress((void**)&p_cur, g_cursor);
    cudaGetSymbolAddress((void**)&p_col, g_col);

    const int GB_N = (NNODES + 255) / 256;
    const int GB_E = (NEDGES + 255) / 256;
    const int GB_W = (NNODES * 32 + 255) / 256;      // warp-per-node kernels
    const dim3 GB_G((NNODES + 127) / 128, 2);        // gemm: row tiles x {s,z}

    // CSR build (per replay)
    k_zero_deg<<<GB_N, 256>>>(p_deg);
    k_count<<<GB_E, 256>>>(rows, p_deg);
    k_scan<<<1, 1024>>>(p_deg, p_rp, p_cur);
    k_fill<<<GB_E, 256>>>(rows, cols, p_cur, p_col);

    // Layer 1: [s|z] = x @ [Wl1|Wr1]^T, then h = relu(s + (A@z)/(deg+1))
    k_gemm_tf32<<<GB_G, 256>>>(x, NFEAT, W1, p_s, p_z);
    k_spmm<<<GB_W, 256>>>(p_z, p_s, p_rp, p_col, p_deg, p_h);

    // Layer 2
    k_gemm_tf32<<<GB_G, 256>>>(p_h, NHID, W2, p_s, p_z);
    k_spmm<<<GB_W, 256>>>(p_z, p_s, p_rp, p_col, p_deg, p_h);

    // MLP + log_softmax
    k_mlp<<<GB_W, 256>>>(p_h, mW, mb, out);
}

// round 4
// speedup vs baseline: 1.6018x; 1.2269x over previous
#include <cuda_runtime.h>
#include <cuda_fp16.h>
#include <math.h>

#define NNODES 100000
#define NEDGES 3200000
#define NFEAT  256
#define NHID   128
#define NCLASS 40

// ---------------- scratch (static device globals; no allocs) ----------------
__device__ float  g_s[(size_t)NNODES * NHID];   // self-projection (fp32)
__device__ __half g_zh[(size_t)NNODES * NHID];  // neighbor-projection (fp16)
__device__ float  g_h[(size_t)NNODES * NHID];   // layer output
__device__ int    g_deg[NNODES];
__device__ int    g_rowptr[NNODES + 1];
__device__ int    g_cursor[NNODES];
__device__ int    g_col[NEDGES];

// ---------------- CSR build ----------------
__global__ void k_zero_deg(int* __restrict__ deg) {
    int i = blockIdx.x * blockDim.x + threadIdx.x;
    if (i < NNODES) deg[i] = 0;
}

__global__ void k_count(const int* __restrict__ rows, int* __restrict__ deg) {
    int e = blockIdx.x * blockDim.x + threadIdx.x;
    if (e < NEDGES) atomicAdd(&deg[rows[e]], 1);
}

__global__ void k_scan(const int* __restrict__ deg, int* __restrict__ rp,
                       int* __restrict__ cur) {
    __shared__ int wsum[32];
    __shared__ int carry;
    int tid = threadIdx.x, lane = tid & 31, wid = tid >> 5;
    if (tid == 0) carry = 0;
    __syncthreads();
    for (int base = 0; base < NNODES; base += 1024) {
        int i = base + tid;
        int v = (i < NNODES) ? deg[i] : 0;
        int x = v;
        #pragma unroll
        for (int d = 1; d < 32; d <<= 1) {
            int y = __shfl_up_sync(0xffffffffu, x, d);
            if (lane >= d) x += y;
        }
        if (lane == 31) wsum[wid] = x;
        __syncthreads();
        if (wid == 0) {
            int s = wsum[lane];
            #pragma unroll
            for (int d = 1; d < 32; d <<= 1) {
                int y = __shfl_up_sync(0xffffffffu, s, d);
                if (lane >= d) s += y;
            }
            wsum[lane] = s;
        }
        __syncthreads();
        int off  = carry + (wid ? wsum[wid - 1] : 0);
        int excl = off + x - v;
        if (i < NNODES) { rp[i] = excl; cur[i] = excl; }
        int tot = wsum[31];
        __syncthreads();
        if (tid == 0) carry += tot;
        __syncthreads();
    }
    if (tid == 0) rp[NNODES] = carry;
}

__global__ void k_fill(const int* __restrict__ rows, const int* __restrict__ cols,
                       int* __restrict__ cur, int* __restrict__ col) {
    int e = blockIdx.x * blockDim.x + threadIdx.x;
    if (e < NEDGES) {
        int p = atomicAdd(&cur[rows[e]], 1);
        col[p] = cols[e];
    }
}

// ---------------- TF32 tensor-core GEMM ----------------
__device__ __forceinline__ unsigned f2tf32(float v) {
    unsigned u;
    asm("cvt.rna.tf32.f32 %0, %1;" : "=r"(u) : "f"(v));
    return u;
}

__device__ __forceinline__ void mma_tf32(float* c, const unsigned* a,
                                         unsigned b0, unsigned b1) {
    asm volatile(
        "mma.sync.aligned.m16n8k8.row.col.f32.tf32.tf32.f32 "
        "{%0,%1,%2,%3}, {%4,%5,%6,%7}, {%8,%9}, {%0,%1,%2,%3};"
        : "+f"(c[0]), "+f"(c[1]), "+f"(c[2]), "+f"(c[3])
        : "r"(a[0]), "r"(a[1]), "r"(a[2]), "r"(a[3]), "r"(b0), "r"(b1));
}

// C = A[M,K] @ Whalf[128,K]^T. W row-major [128, 2K]; blockIdx.y picks half:
// y==0 -> fp32 store to s, y==1 -> fp16 store to zh.
__global__ __launch_bounds__(256) void k_gemm_tf32(
    const float* __restrict__ A, int K,
    const float* __restrict__ W,
    float* __restrict__ Cs, __half* __restrict__ Czh)
{
    __shared__ unsigned As[32][132];
    __shared__ unsigned Bs[32][132];
    const int tid = threadIdx.x, lane = tid & 31, wid = tid >> 5;
    const int warpM = wid & 3, warpN = wid >> 2;
    const int row0 = blockIdx.x * 128;
    const int ldw = 2 * K;
    const float* Wb = W + (size_t)blockIdx.y * K;

    float acc[2][8][4];
    #pragma unroll
    for (int mi = 0; mi < 2; mi++)
        #pragma unroll
        for (int ni = 0; ni < 8; ni++)
            #pragma unroll
            for (int q = 0; q < 4; q++) acc[mi][ni][q] = 0.f;

    for (int k0 = 0; k0 < K; k0 += 32) {
        #pragma unroll
        for (int j = 0; j < 4; j++) {
            int i  = tid + j * 256;
            int r  = i >> 3;
            int c4 = (i & 7) * 4;
            float4 v = make_float4(0.f, 0.f, 0.f, 0.f);
            if (row0 + r < NNODES)
                v = *(const float4*)(A + (size_t)(row0 + r) * K + k0 + c4);
            As[c4 + 0][r] = f2tf32(v.x); As[c4 + 1][r] = f2tf32(v.y);
            As[c4 + 2][r] = f2tf32(v.z); As[c4 + 3][r] = f2tf32(v.w);
        }
        #pragma unroll
        for (int j = 0; j < 4; j++) {
            int i  = tid + j * 256;
            int n  = i >> 3;
            int c4 = (i & 7) * 4;
            float4 v = *(const float4*)(Wb + (size_t)n * ldw + k0 + c4);
            Bs[c4 + 0][n] = f2tf32(v.x); Bs[c4 + 1][n] = f2tf32(v.y);
            Bs[c4 + 2][n] = f2tf32(v.z); Bs[c4 + 3][n] = f2tf32(v.w);
        }
        __syncthreads();

        #pragma unroll
        for (int kk = 0; kk < 32; kk += 8) {
            unsigned af[2][4];
            const int kc = kk + (lane & 3);
            #pragma unroll
            for (int mi = 0; mi < 2; mi++) {
                int r = warpM * 32 + mi * 16 + (lane >> 2);
                af[mi][0] = As[kc][r];
                af[mi][1] = As[kc][r + 8];
                af[mi][2] = As[kc + 4][r];
                af[mi][3] = As[kc + 4][r + 8];
            }
            #pragma unroll
            for (int ni = 0; ni < 8; ni++) {
                int n = warpN * 64 + ni * 8 + (lane >> 2);
                unsigned b0 = Bs[kc][n];
                unsigned b1 = Bs[kc + 4][n];
                mma_tf32(acc[0][ni], af[0], b0, b1);
                mma_tf32(acc[1][ni], af[1], b0, b1);
            }
        }
        __syncthreads();
    }

    #pragma unroll
    for (int mi = 0; mi < 2; mi++) {
        int rbase = row0 + warpM * 32 + mi * 16 + (lane >> 2);
        #pragma unroll
        for (int ni = 0; ni < 8; ni++) {
            int col = warpN * 64 + ni * 8 + 2 * (lane & 3);
            if (blockIdx.y == 0) {
                if (rbase < NNODES)
                    *(float2*)(Cs + (size_t)rbase * NHID + col) =
                        make_float2(acc[mi][ni][0], acc[mi][ni][1]);
                if (rbase + 8 < NNODES)
                    *(float2*)(Cs + (size_t)(rbase + 8) * NHID + col) =
                        make_float2(acc[mi][ni][2], acc[mi][ni][3]);
            } else {
                if (rbase < NNODES)
                    *(__half2*)(Czh + (size_t)rbase * NHID + col) =
                        __floats2half2_rn(acc[mi][ni][0], acc[mi][ni][1]);
                if (rbase + 8 < NNODES)
                    *(__half2*)(Czh + (size_t)(rbase + 8) * NHID + col) =
                        __floats2half2_rn(acc[mi][ni][2], acc[mi][ni][3]);
            }
        }
    }
}

// ---------------- SpMM + epilogue: h = relu(s + (A@z)/(deg+1)), z fp16 ----------------
__global__ __launch_bounds__(256) void k_spmm(const __half* __restrict__ zh,
                                              const float* __restrict__ s,
                                              const int* __restrict__ rp,
                                              const int* __restrict__ col,
                                              float* __restrict__ h) {
    int lane = threadIdx.x & 31;
    int n    = (blockIdx.x * 256 + threadIdx.x) >> 5;
    if (n >= NNODES) return;
    int e = rp[n], end = rp[n + 1];
    int deg = end - e;
    float ax = 0.f, ay = 0.f, az = 0.f, aw = 0.f;
    for (; e + 2 <= end; e += 2) {
        int c0 = col[e], c1 = col[e + 1];
        uint2 u0 = *(const uint2*)(zh + (size_t)c0 * NHID + lane * 4);
        uint2 u1 = *(const uint2*)(zh + (size_t)c1 * NHID + lane * 4);
        float2 p0 = __half22float2(*(__half2*)&u0.x);
        float2 p1 = __half22float2(*(__half2*)&u0.y);
        float2 q0 = __half22float2(*(__half2*)&u1.x);
        float2 q1 = __half22float2(*(__half2*)&u1.y);
        ax += p0.x + q0.x; ay += p0.y + q0.y;
        az += p1.x + q1.x; aw += p1.y + q1.y;
    }
    if (e < end) {
        int c0 = col[e];
        uint2 u0 = *(const uint2*)(zh + (size_t)c0 * NHID + lane * 4);
        float2 p0 = __half22float2(*(__half2*)&u0.x);
        float2 p1 = __half22float2(*(__half2*)&u0.y);
        ax += p0.x; ay += p0.y; az += p1.x; aw += p1.y;
    }
    float inv = 1.0f / (1.0f + (float)deg);
    float4 sv = *(const float4*)(s + (size_t)n * NHID + lane * 4);
    float4 o;
    o.x = fmaxf(fmaf(ax, inv, sv.x), 0.f);
    o.y = fmaxf(fmaf(ay, inv, sv.y), 0.f);
    o.z = fmaxf(fmaf(az, inv, sv.z), 0.f);
    o.w = fmaxf(fmaf(aw, inv, sv.w), 0.f);
    *(float4*)(h + (size_t)n * NHID + lane * 4) = o;
}

// ---------------- MLP + log_softmax via tensor cores ----------------
// Block: 128 threads, 128 nodes. logits = h[128rows,128] @ mW[40,128]^T + b.
__global__ __launch_bounds__(128) void k_mlp_tc(const float* __restrict__ h,
                                                const float* __restrict__ Wm,
                                                const float* __restrict__ b,
                                                float* __restrict__ out) {
    __shared__ unsigned As[32][132];      // [k][m]
    __shared__ unsigned Bsm[NCLASS][132]; // [n][k] = mW layout, padded
    __shared__ float    Ls[128][41];      // logits, odd stride
    __shared__ float    bs[NCLASS];

    const int tid = threadIdx.x, lane = tid & 31, wid = tid >> 5;
    const int row0 = blockIdx.x * 128;

    // weights + bias into smem (once)
    for (int i = tid; i < NCLASS * NHID; i += 128)
        Bsm[i >> 7][i & 127] = f2tf32(Wm[i]);
    if (tid < NCLASS) bs[tid] = b[tid];

    float acc[2][5][4];
    #pragma unroll
    for (int mi = 0; mi < 2; mi++)
        #pragma unroll
        for (int ni = 0; ni < 5; ni++)
            #pragma unroll
            for (int q = 0; q < 4; q++) acc[mi][ni][q] = 0.f;

    for (int k0 = 0; k0 < NHID; k0 += 32) {
        #pragma unroll
        for (int j = 0; j < 8; j++) {
            int i  = tid + j * 128;
            int r  = i >> 3;
            int c4 = (i & 7) * 4;
            float4 v = make_float4(0.f, 0.f, 0.f, 0.f);
            if (row0 + r < NNODES)
                v = *(const float4*)(h + (size_t)(row0 + r) * NHID + k0 + c4);
            As[c4 + 0][r] = f2tf32(v.x); As[c4 + 1][r] = f2tf32(v.y);
            As[c4 + 2][r] = f2tf32(v.z); As[c4 + 3][r] = f2tf32(v.w);
        }
        __syncthreads();

        #pragma unroll
        for (int kk = 0; kk < 32; kk += 8) {
            const int kc = kk + (lane & 3);
            unsigned af[2][4];
            #pragma unroll
            for (int mi = 0; mi < 2; mi++) {
                int r = wid * 32 + mi * 16 + (lane >> 2);
                af[mi][0] = As[kc][r];
                af[mi][1] = As[kc][r + 8];
                af[mi][2] = As[kc + 4][r];
                af[mi][3] = As[kc + 4][r + 8];
            }
            #pragma unroll
            for (int ni = 0; ni < 5; ni++) {
                int n = ni * 8 + (lane >> 2);
                unsigned b0 = Bsm[n][k0 + kc];
                unsigned b1 = Bsm[n][k0 + kc + 4];
                mma_tf32(acc[0][ni], af[0], b0, b1);
                mma_tf32(acc[1][ni], af[1], b0, b1);
            }
        }
        __syncthreads();
    }

    // stage logits
    #pragma unroll
    for (int mi = 0; mi < 2; mi++) {
        int r = wid * 32 + mi * 16 + (lane >> 2);
        #pragma unroll
        for (int ni = 0; ni < 5; ni++) {
            int c = ni * 8 + 2 * (lane & 3);
            Ls[r][c]         = acc[mi][ni][0];
            Ls[r][c + 1]     = acc[mi][ni][1];
            Ls[r + 8][c]     = acc[mi][ni][2];
            Ls[r + 8][c + 1] = acc[mi][ni][3];
        }
    }
    __syncthreads();

    // per-thread row log_softmax
    int gr = row0 + tid;
    if (gr >= NNODES) return;
    float l[NCLASS];
    float m = -INFINITY;
    #pragma unroll
    for (int c = 0; c < NCLASS; c++) {
        l[c] = Ls[tid][c] + bs[c];
        m = fmaxf(m, l[c]);
    }
    float se = 0.f;
    #pragma unroll
    for (int c = 0; c < NCLASS; c++) se += expf(l[c] - m);
    float lse = m + logf(se);
    float* op = out + (size_t)gr * NCLASS;
    #pragma unroll
    for (int c = 0; c < NCLASS; c += 4)
        *(float4*)(op + c) = make_float4(l[c] - lse, l[c + 1] - lse,
                                         l[c + 2] - lse, l[c + 3] - lse);
}

// ---------------- launch ----------------
extern "C" void kernel_launch(void* const* d_in, const int* in_sizes, int n_in,
                              void* d_out, int out_size) {
    const float* x    = (const float*)d_in[0];
    const float* W1   = (const float*)d_in[1];   // [128, 512]
    const float* W2   = (const float*)d_in[2];   // [128, 256]
    const float* mW   = (const float*)d_in[3];   // [40, 128]
    const float* mb   = (const float*)d_in[4];   // [40]
    const int*   rows = (const int*)d_in[5];
    const int*   cols = (const int*)d_in[6];
    float*       out  = (float*)d_out;

    float *p_s, *p_h;
    __half* p_zh;
    int *p_deg, *p_rp, *p_cur, *p_col;
    cudaGetSymbolAddress((void**)&p_s,   g_s);
    cudaGetSymbolAddress((void**)&p_zh,  g_zh);
    cudaGetSymbolAddress((void**)&p_h,   g_h);
    cudaGetSymbolAddress((void**)&p_deg, g_deg);
    cudaGetSymbolAddress((void**)&p_rp,  g_rowptr);
    cudaGetSymbolAddress((void**)&p_cur, g_cursor);
    cudaGetSymbolAddress((void**)&p_col, g_col);

    const int GB_N = (NNODES + 255) / 256;
    const int GB_E = (NEDGES + 255) / 256;
    const int GB_W = (NNODES * 32 + 255) / 256;
    const int GB_T = (NNODES + 127) / 128;
    const dim3 GB_G(GB_T, 2);

    // CSR build (per replay)
    k_zero_deg<<<GB_N, 256>>>(p_deg);
    k_count<<<GB_E, 256>>>(rows, p_deg);
    k_scan<<<1, 1024>>>(p_deg, p_rp, p_cur);
    k_fill<<<GB_E, 256>>>(rows, cols, p_cur, p_col);

    // Layer 1
    k_gemm_tf32<<<GB_G, 256>>>(x, NFEAT, W1, p_s, p_zh);
    k_spmm<<<GB_W, 256>>>(p_zh, p_s, p_rp, p_col, p_h);

    // Layer 2
    k_gemm_tf32<<<GB_G, 256>>>(p_h, NHID, W2, p_s, p_zh);
    k_spmm<<<GB_W, 256>>>(p_zh, p_s, p_rp, p_col, p_h);

    // MLP + log_softmax
    k_mlp_tc<<<GB_T, 128>>>(p_h, mW, mb, out);
}

// round 6
// speedup vs baseline: 1.9267x; 1.2028x over previous
#include <cuda_runtime.h>
#include <cuda_fp16.h>
#include <cuda_bf16.h>
#include <math.h>

#define NNODES 100000
#define NEDGES 3200000
#define NFEAT  256
#define NHID   128
#define NCLASS 40

// ---------------- scratch (static device globals; no allocs) ----------------
__device__ float  g_s[(size_t)NNODES * NHID];   // self-projection (fp32)
__device__ __half g_zh[(size_t)NNODES * NHID];  // neighbor-projection (fp16)
__device__ float  g_h[(size_t)NNODES * NHID];   // layer output
__device__ int    g_deg[NNODES];
__device__ int    g_rowptr[NNODES + 1];
__device__ int    g_cursor[NNODES];
__device__ int    g_col[NEDGES];

// ---------------- CSR build ----------------
__global__ void k_count(const int* __restrict__ rows, int* __restrict__ deg) {
    int e = blockIdx.x * blockDim.x + threadIdx.x;
    if (e < NEDGES) atomicAdd(&deg[rows[e]], 1);
}

__global__ void k_scan(const int* __restrict__ deg, int* __restrict__ rp,
                       int* __restrict__ cur) {
    __shared__ int wsum[32];
    __shared__ int carry;
    int tid = threadIdx.x, lane = tid & 31, wid = tid >> 5;
    if (tid == 0) carry = 0;
    __syncthreads();
    for (int base = 0; base < NNODES; base += 1024) {
        int i = base + tid;
        int v = (i < NNODES) ? deg[i] : 0;
        int x = v;
        #pragma unroll
        for (int d = 1; d < 32; d <<= 1) {
            int y = __shfl_up_sync(0xffffffffu, x, d);
            if (lane >= d) x += y;
        }
        if (lane == 31) wsum[wid] = x;
        __syncthreads();
        if (wid == 0) {
            int s = wsum[lane];
            #pragma unroll
            for (int d = 1; d < 32; d <<= 1) {
                int y = __shfl_up_sync(0xffffffffu, s, d);
                if (lane >= d) s += y;
            }
            wsum[lane] = s;
        }
        __syncthreads();
        int off  = carry + (wid ? wsum[wid - 1] : 0);
        int excl = off + x - v;
        if (i < NNODES) { rp[i] = excl; cur[i] = excl; }
        int tot = wsum[31];
        __syncthreads();
        if (tid == 0) carry += tot;
        __syncthreads();
    }
    if (tid == 0) rp[NNODES] = carry;
}

__global__ void k_fill(const int* __restrict__ rows, const int* __restrict__ cols,
                       int* __restrict__ cur, int* __restrict__ col) {
    int e = blockIdx.x * blockDim.x + threadIdx.x;
    if (e < NEDGES) {
        int p = atomicAdd(&cur[rows[e]], 1);
        col[p] = cols[e];
    }
}

// ---------------- bf16 tensor-core helpers ----------------
__device__ __forceinline__ unsigned pack_bf16x2(float lo, float hi) {
    unsigned u;
    asm("cvt.rn.bf16x2.f32 %0, %1, %2;" : "=r"(u) : "f"(hi), "f"(lo));
    return u;
}

__device__ __forceinline__ void mma_bf16(float* c, const unsigned* a,
                                         unsigned b0, unsigned b1) {
    asm volatile(
        "mma.sync.aligned.m16n8k16.row.col.f32.bf16.bf16.f32 "
        "{%0,%1,%2,%3}, {%4,%5,%6,%7}, {%8,%9}, {%0,%1,%2,%3};"
        : "+f"(c[0]), "+f"(c[1]), "+f"(c[2]), "+f"(c[3])
        : "r"(a[0]), "r"(a[1]), "r"(a[2]), "r"(a[3]), "r"(b0), "r"(b1));
}

__device__ __forceinline__ unsigned f2tf32(float v) {
    unsigned u;
    asm("cvt.rna.tf32.f32 %0, %1;" : "=r"(u) : "f"(v));
    return u;
}

__device__ __forceinline__ void mma_tf32(float* c, const unsigned* a,
                                         unsigned b0, unsigned b1) {
    asm volatile(
        "mma.sync.aligned.m16n8k8.row.col.f32.tf32.tf32.f32 "
        "{%0,%1,%2,%3}, {%4,%5,%6,%7}, {%8,%9}, {%0,%1,%2,%3};"
        : "+f"(c[0]), "+f"(c[1]), "+f"(c[2]), "+f"(c[3])
        : "r"(a[0]), "r"(a[1]), "r"(a[2]), "r"(a[3]), "r"(b0), "r"(b1));
}

// ---------------- bf16 GEMM: C = A[M,K] @ Whalf[128,K]^T ----------------
// W row-major [128, 2K]; blockIdx.y: 0 -> fp32 store to s, 1 -> fp16 store to zh.
// Smem tiles packed as half2-pairs along k: As[k2][m] holds k={2*k2, 2*k2+1}.
__global__ __launch_bounds__(256) void k_gemm_bf16(
    const float* __restrict__ A, int K,
    const float* __restrict__ W,
    float* __restrict__ Cs, __half* __restrict__ Czh)
{
    __shared__ unsigned As[16][132];   // 32 k x 128 m (bf16x2)
    __shared__ unsigned Bs[16][132];   // 32 k x 128 n
    const int tid = threadIdx.x, lane = tid & 31, wid = tid >> 5;
    const int warpM = wid & 3, warpN = wid >> 2;     // 4x2 warp grid, 32x64 tiles
    const int row0 = blockIdx.x * 128;
    const int ldw = 2 * K;
    const float* Wb = W + (size_t)blockIdx.y * K;

    float acc[2][8][4];
    #pragma unroll
    for (int mi = 0; mi < 2; mi++)
        #pragma unroll
        for (int ni = 0; ni < 8; ni++)
            #pragma unroll
            for (int q = 0; q < 4; q++) acc[mi][ni][q] = 0.f;

    for (int k0 = 0; k0 < K; k0 += 32) {
        // A tile: 128 rows x 32 k. thread loads float4 -> 2 bf16x2 words
        #pragma unroll
        for (int j = 0; j < 4; j++) {
            int i  = tid + j * 256;
            int r  = i >> 3;
            int c2 = (i & 7) * 2;      // k2 index
            float4 v = make_float4(0.f, 0.f, 0.f, 0.f);
            if (row0 + r < NNODES)
                v = *(const float4*)(A + (size_t)(row0 + r) * K + k0 + c2 * 2);
            As[c2 + 0][r] = pack_bf16x2(v.x, v.y);
            As[c2 + 1][r] = pack_bf16x2(v.z, v.w);
        }
        // B tile: 128 n-rows x 32 k
        #pragma unroll
        for (int j = 0; j < 4; j++) {
            int i  = tid + j * 256;
            int n  = i >> 3;
            int c2 = (i & 7) * 2;
            float4 v = *(const float4*)(Wb + (size_t)n * ldw + k0 + c2 * 2);
            Bs[c2 + 0][n] = pack_bf16x2(v.x, v.y);
            Bs[c2 + 1][n] = pack_bf16x2(v.z, v.w);
        }
        __syncthreads();

        #pragma unroll
        for (int ks = 0; ks < 2; ks++) {           // two k16 steps
            const int k2b = ks * 8 + (lane & 3);
            unsigned af[2][4];
            #pragma unroll
            for (int mi = 0; mi < 2; mi++) {
                int r = warpM * 32 + mi * 16 + (lane >> 2);
                af[mi][0] = As[k2b][r];
                af[mi][1] = As[k2b][r + 8];
                af[mi][2] = As[k2b + 4][r];
                af[mi][3] = As[k2b + 4][r + 8];
            }
            #pragma unroll
            for (int ni = 0; ni < 8; ni++) {
                int n = warpN * 64 + ni * 8 + (lane >> 2);
                unsigned b0 = Bs[k2b][n];
                unsigned b1 = Bs[k2b + 4][n];
                mma_bf16(acc[0][ni], af[0], b0, b1);
                mma_bf16(acc[1][ni], af[1], b0, b1);
            }
        }
        __syncthreads();
    }

    #pragma unroll
    for (int mi = 0; mi < 2; mi++) {
        int rbase = row0 + warpM * 32 + mi * 16 + (lane >> 2);
        #pragma unroll
        for (int ni = 0; ni < 8; ni++) {
            int col = warpN * 64 + ni * 8 + 2 * (lane & 3);
            if (blockIdx.y == 0) {
                if (rbase < NNODES)
                    *(float2*)(Cs + (size_t)rbase * NHID + col) =
                        make_float2(acc[mi][ni][0], acc[mi][ni][1]);
                if (rbase + 8 < NNODES)
                    *(float2*)(Cs + (size_t)(rbase + 8) * NHID + col) =
                        make_float2(acc[mi][ni][2], acc[mi][ni][3]);
            } else {
                if (rbase < NNODES)
                    *(__half2*)(Czh + (size_t)rbase * NHID + col) =
                        __floats2half2_rn(acc[mi][ni][0], acc[mi][ni][1]);
                if (rbase + 8 < NNODES)
                    *(__half2*)(Czh + (size_t)(rbase + 8) * NHID + col) =
                        __floats2half2_rn(acc[mi][ni][2], acc[mi][ni][3]);
            }
        }
    }
}

// ---------------- SpMM + epilogue: h = relu(s + (A@z)/(deg+1)), z fp16 ----------------
__global__ __launch_bounds__(256) void k_spmm(const __half* __restrict__ zh,
                                              const float* __restrict__ s,
                                              const int* __restrict__ rp,
                                              const int* __restrict__ col,
                                              float* __restrict__ h) {
    int lane = threadIdx.x & 31;
    int n    = (blockIdx.x * 256 + threadIdx.x) >> 5;
    if (n >= NNODES) return;
    int e = rp[n], end = rp[n + 1];
    int deg = end - e;
    float ax = 0.f, ay = 0.f, az = 0.f, aw = 0.f;
    for (; e + 2 <= end; e += 2) {
        int c0 = col[e], c1 = col[e + 1];
        uint2 u0 = *(const uint2*)(zh + (size_t)c0 * NHID + lane * 4);
        uint2 u1 = *(const uint2*)(zh + (size_t)c1 * NHID + lane * 4);
        float2 p0 = __half22float2(*(__half2*)&u0.x);
        float2 p1 = __half22float2(*(__half2*)&u0.y);
        float2 q0 = __half22float2(*(__half2*)&u1.x);
        float2 q1 = __half22float2(*(__half2*)&u1.y);
        ax += p0.x + q0.x; ay += p0.y + q0.y;
        az += p1.x + q1.x; aw += p1.y + q1.y;
    }
    if (e < end) {
        int c0 = col[e];
        uint2 u0 = *(const uint2*)(zh + (size_t)c0 * NHID + lane * 4);
        float2 p0 = __half22float2(*(__half2*)&u0.x);
        float2 p1 = __half22float2(*(__half2*)&u0.y);
        ax += p0.x; ay += p0.y; az += p1.x; aw += p1.y;
    }
    float inv = 1.0f / (1.0f + (float)deg);
    float4 sv = *(const float4*)(s + (size_t)n * NHID + lane * 4);
    float4 o;
    o.x = fmaxf(fmaf(ax, inv, sv.x), 0.f);
    o.y = fmaxf(fmaf(ay, inv, sv.y), 0.f);
    o.z = fmaxf(fmaf(az, inv, sv.z), 0.f);
    o.w = fmaxf(fmaf(aw, inv, sv.w), 0.f);
    *(float4*)(h + (size_t)n * NHID + lane * 4) = o;
}

// ---------------- MLP + log_softmax via tensor cores (tf32) ----------------
__global__ __launch_bounds__(128) void k_mlp_tc(const float* __restrict__ h,
                                                const float* __restrict__ Wm,
                                                const float* __restrict__ b,
                                                float* __restrict__ out) {
    __shared__ unsigned As[32][132];      // [k][m]
    __shared__ unsigned Bsm[NCLASS][132]; // [n][k]
    __shared__ float    Ls[128][41];
    __shared__ float    bs[NCLASS];

    const int tid = threadIdx.x, lane = tid & 31, wid = tid >> 5;
    const int row0 = blockIdx.x * 128;

    for (int i = tid; i < NCLASS * NHID; i += 128)
        Bsm[i >> 7][i & 127] = f2tf32(Wm[i]);
    if (tid < NCLASS) bs[tid] = b[tid];

    float acc[2][5][4];
    #pragma unroll
    for (int mi = 0; mi < 2; mi++)
        #pragma unroll
        for (int ni = 0; ni < 5; ni++)
            #pragma unroll
            for (int q = 0; q < 4; q++) acc[mi][ni][q] = 0.f;

    for (int k0 = 0; k0 < NHID; k0 += 32) {
        #pragma unroll
        for (int j = 0; j < 8; j++) {
            int i  = tid + j * 128;
            int r  = i >> 3;
            int c4 = (i & 7) * 4;
            float4 v = make_float4(0.f, 0.f, 0.f, 0.f);
            if (row0 + r < NNODES)
                v = *(const float4*)(h + (size_t)(row0 + r) * NHID + k0 + c4);
            As[c4 + 0][r] = f2tf32(v.x); As[c4 + 1][r] = f2tf32(v.y);
            As[c4 + 2][r] = f2tf32(v.z); As[c4 + 3][r] = f2tf32(v.w);
        }
        __syncthreads();

        #pragma unroll
        for (int kk = 0; kk < 32; kk += 8) {
            const int kc = kk + (lane & 3);
            unsigned af[2][4];
            #pragma unroll
            for (int mi = 0; mi < 2; mi++) {
                int r = wid * 32 + mi * 16 + (lane >> 2);
                af[mi][0] = As[kc][r];
                af[mi][1] = As[kc][r + 8];
                af[mi][2] = As[kc + 4][r];
                af[mi][3] = As[kc + 4][r + 8];
            }
            #pragma unroll
            for (int ni = 0; ni < 5; ni++) {
                int n = ni * 8 + (lane >> 2);
                unsigned b0 = Bsm[n][k0 + kc];
                unsigned b1 = Bsm[n][k0 + kc + 4];
                mma_tf32(acc[0][ni], af[0], b0, b1);
                mma_tf32(acc[1][ni], af[1], b0, b1);
            }
        }
        __syncthreads();
    }

    #pragma unroll
    for (int mi = 0; mi < 2; mi++) {
        int r = wid * 32 + mi * 16 + (lane >> 2);
        #pragma unroll
        for (int ni = 0; ni < 5; ni++) {
            int c = ni * 8 + 2 * (lane & 3);
            Ls[r][c]         = acc[mi][ni][0];
            Ls[r][c + 1]     = acc[mi][ni][1];
            Ls[r + 8][c]     = acc[mi][ni][2];
            Ls[r + 8][c + 1] = acc[mi][ni][3];
        }
    }
    __syncthreads();

    int gr = row0 + tid;
    if (gr >= NNODES) return;
    float l[NCLASS];
    float m = -INFINITY;
    #pragma unroll
    for (int c = 0; c < NCLASS; c++) {
        l[c] = Ls[tid][c] + bs[c];
        m = fmaxf(m, l[c]);
    }
    float se = 0.f;
    #pragma unroll
    for (int c = 0; c < NCLASS; c++) se += expf(l[c] - m);
    float lse = m + logf(se);
    float* op = out + (size_t)gr * NCLASS;
    #pragma unroll
    for (int c = 0; c < NCLASS; c += 4)
        *(float4*)(op + c) = make_float4(l[c] - lse, l[c + 1] - lse,
                                         l[c + 2] - lse, l[c + 3] - lse);
}

// ---------------- launch ----------------
extern "C" void kernel_launch(void* const* d_in, const int* in_sizes, int n_in,
                              void* d_out, int out_size) {
    const float* x    = (const float*)d_in[0];
    const float* W1   = (const float*)d_in[1];   // [128, 512]
    const float* W2   = (const float*)d_in[2];   // [128, 256]
    const float* mW   = (const float*)d_in[3];   // [40, 128]
    const float* mb   = (const float*)d_in[4];   // [40]
    const int*   rows = (const int*)d_in[5];
    const int*   cols = (const int*)d_in[6];
    float*       out  = (float*)d_out;

    float *p_s, *p_h;
    __half* p_zh;
    int *p_deg, *p_rp, *p_cur, *p_col;
    cudaGetSymbolAddress((void**)&p_s,   g_s);
    cudaGetSymbolAddress((void**)&p_zh,  g_zh);
    cudaGetSymbolAddress((void**)&p_h,   g_h);
    cudaGetSymbolAddress((void**)&p_deg, g_deg);
    cudaGetSymbolAddress((void**)&p_rp,  g_rowptr);
    cudaGetSymbolAddress((void**)&p_cur, g_cursor);
    cudaGetSymbolAddress((void**)&p_col, g_col);

    const int GB_E = (NEDGES + 255) / 256;
    const int GB_W = (NNODES * 32 + 255) / 256;
    const int GB_T = (NNODES + 127) / 128;
    const dim3 GB_G(GB_T, 2);

    // CSR build (per replay)
    cudaMemsetAsync(p_deg, 0, NNODES * sizeof(int));
    k_count<<<GB_E, 256>>>(rows, p_deg);
    k_scan<<<1, 1024>>>(p_deg, p_rp, p_cur);
    k_fill<<<GB_E, 256>>>(rows, cols, p_cur, p_col);

    // Layer 1
    k_gemm_bf16<<<GB_G, 256>>>(x, NFEAT, W1, p_s, p_zh);
    k_spmm<<<GB_W, 256>>>(p_zh, p_s, p_rp, p_col, p_h);

    // Layer 2
    k_gemm_bf16<<<GB_G, 256>>>(p_h, NHID, W2, p_s, p_zh);
    k_spmm<<<GB_W, 256>>>(p_zh, p_s, p_rp, p_col, p_h);

    // MLP + log_softmax
    k_mlp_tc<<<GB_T, 128>>>(p_h, mW, mb, out);
}

// round 7
// speedup vs baseline: 2.5770x; 1.3376x over previous
#include <cuda_runtime.h>
#include <cuda_fp16.h>
#include <cuda_bf16.h>
#include <math.h>

#define NNODES 100000
#define NEDGES 3200000
#define NFEAT  256
#define NHID   128
#define NCLASS 40

// ---------------- scratch (static device globals; no allocs) ----------------
__device__ float          g_s[(size_t)NNODES * NHID];    // self-projection fp32
__device__ __half         g_zh[(size_t)NNODES * NHID];   // neighbor proj fp16
__device__ __nv_bfloat16  g_hb[(size_t)NNODES * NHID];   // layer output bf16
__device__ __nv_bfloat16  g_xb[(size_t)NNODES * NFEAT];  // x in bf16
__device__ __nv_bfloat16  g_w1b[NHID * 2 * NFEAT];
__device__ __nv_bfloat16  g_w2b[NHID * 2 * NHID];
__device__ int            g_deg[NNODES];
__device__ int            g_rowptr[NNODES + 1];
__device__ int            g_cursor[NNODES];
__device__ int            g_col[NEDGES];

// ---------------- helpers ----------------
__device__ __forceinline__ unsigned pack_bf16x2(float lo, float hi) {
    unsigned u;
    asm("cvt.rn.bf16x2.f32 %0, %1, %2;" : "=r"(u) : "f"(hi), "f"(lo));
    return u;
}
__device__ __forceinline__ unsigned f2tf32(float v) {
    unsigned u;
    asm("cvt.rna.tf32.f32 %0, %1;" : "=r"(u) : "f"(v));
    return u;
}
__device__ __forceinline__ void mma_bf16(float* c, const unsigned* a,
                                         unsigned b0, unsigned b1) {
    asm volatile(
        "mma.sync.aligned.m16n8k16.row.col.f32.bf16.bf16.f32 "
        "{%0,%1,%2,%3}, {%4,%5,%6,%7}, {%8,%9}, {%0,%1,%2,%3};"
        : "+f"(c[0]), "+f"(c[1]), "+f"(c[2]), "+f"(c[3])
        : "r"(a[0]), "r"(a[1]), "r"(a[2]), "r"(a[3]), "r"(b0), "r"(b1));
}
__device__ __forceinline__ void mma_tf32(float* c, const unsigned* a,
                                         unsigned b0, unsigned b1) {
    asm volatile(
        "mma.sync.aligned.m16n8k8.row.col.f32.tf32.tf32.f32 "
        "{%0,%1,%2,%3}, {%4,%5,%6,%7}, {%8,%9}, {%0,%1,%2,%3};"
        : "+f"(c[0]), "+f"(c[1]), "+f"(c[2]), "+f"(c[3])
        : "r"(a[0]), "r"(a[1]), "r"(a[2]), "r"(a[3]), "r"(b0), "r"(b1));
}
__device__ __forceinline__ unsigned s2u(const void* p) {
    return (unsigned)__cvta_generic_to_shared(p);
}
__device__ __forceinline__ void cp16(unsigned dst, const void* src, bool pred) {
    int sz = pred ? 16 : 0;
    asm volatile("cp.async.cg.shared.global [%0], [%1], 16, %2;"
                 :: "r"(dst), "l"(src), "r"(sz));
}
#define CP_COMMIT() asm volatile("cp.async.commit_group;")
#define CP_WAIT1()  asm volatile("cp.async.wait_group 1;")
#define CP_WAIT0()  asm volatile("cp.async.wait_group 0;")

// ---------------- fp32 -> bf16 convert ----------------
__global__ void k_cvt(const float* __restrict__ in, __nv_bfloat16* __restrict__ out,
                      int n4) {
    int i = blockIdx.x * blockDim.x + threadIdx.x;
    if (i < n4) {
        float4 v = ((const float4*)in)[i];
        ((uint2*)out)[i] = make_uint2(pack_bf16x2(v.x, v.y), pack_bf16x2(v.z, v.w));
    }
}

// ---------------- CSR build ----------------
__global__ void k_count(const int* __restrict__ rows, int* __restrict__ deg) {
    int e = blockIdx.x * blockDim.x + threadIdx.x;
    if (e < NEDGES) atomicAdd(&deg[rows[e]], 1);
}

__global__ void k_scan(const int* __restrict__ deg, int* __restrict__ rp,
                       int* __restrict__ cur) {
    __shared__ int wsum[32];
    __shared__ int carry;
    int tid = threadIdx.x, lane = tid & 31, wid = tid >> 5;
    if (tid == 0) carry = 0;
    __syncthreads();
    for (int base = 0; base < NNODES; base += 1024) {
        int i = base + tid;
        int v = (i < NNODES) ? deg[i] : 0;
        int x = v;
        #pragma unroll
        for (int d = 1; d < 32; d <<= 1) {
            int y = __shfl_up_sync(0xffffffffu, x, d);
            if (lane >= d) x += y;
        }
        if (lane == 31) wsum[wid] = x;
        __syncthreads();
        if (wid == 0) {
            int s = wsum[lane];
            #pragma unroll
            for (int d = 1; d < 32; d <<= 1) {
                int y = __shfl_up_sync(0xffffffffu, s, d);
                if (lane >= d) s += y;
            }
            wsum[lane] = s;
        }
        __syncthreads();
        int off  = carry + (wid ? wsum[wid - 1] : 0);
        int excl = off + x - v;
        if (i < NNODES) { rp[i] = excl; cur[i] = excl; }
        int tot = wsum[31];
        __syncthreads();
        if (tid == 0) carry += tot;
        __syncthreads();
    }
    if (tid == 0) rp[NNODES] = carry;
}

__global__ void k_fill(const int* __restrict__ rows, const int* __restrict__ cols,
                       int* __restrict__ cur, int* __restrict__ col) {
    int e = blockIdx.x * blockDim.x + threadIdx.x;
    if (e < NEDGES) {
        int p = atomicAdd(&cur[rows[e]], 1);
        col[p] = cols[e];
    }
}

// ---------------- pipelined bf16 GEMM ----------------
// C = A[M,K]_bf16 @ Whalf[128,K]_bf16^T. Wb row-major [128, 2K]; blockIdx.y
// selects half: 0 -> fp32 to s, 1 -> fp16 to zh.
// Smem pitch 80B (20 banks) -> conflict-free 8row x 4word fragment LDS.
#define PITCH 80
__global__ __launch_bounds__(256) void k_gemm_bf16(
    const __nv_bfloat16* __restrict__ A, int K,
    const __nv_bfloat16* __restrict__ W,
    float* __restrict__ Cs, __half* __restrict__ Czh)
{
    __shared__ __align__(16) unsigned char smA[2][128 * PITCH];
    __shared__ __align__(16) unsigned char smB[2][128 * PITCH];
    const int tid = threadIdx.x, lane = tid & 31, wid = tid >> 5;
    const int warpM = wid & 3, warpN = wid >> 2;   // 4x2 warps, 32x64 tiles
    const int row0 = blockIdx.x * 128;
    const int ldw = 2 * K;
    const __nv_bfloat16* Wb = W + (size_t)blockIdx.y * K;
    const int NT = K >> 5;

    // per-thread load coords (2 chunks of 16B for A, 2 for B per tile)
    const int lr0 = tid >> 2, lc0 = tid & 3;          // i = tid
    const int lr1 = (tid + 256) >> 2, lc1 = lc0;      // i = tid + 256
    const bool p0 = (row0 + lr0) < NNODES;
    const bool p1 = (row0 + lr1) < NNODES;

    float acc[2][8][4];
    #pragma unroll
    for (int mi = 0; mi < 2; mi++)
        #pragma unroll
        for (int ni = 0; ni < 8; ni++)
            #pragma unroll
            for (int q = 0; q < 4; q++) acc[mi][ni][q] = 0.f;

    // prologue: tile 0 -> buf 0
    {
        int k0 = 0;
        cp16(s2u(smA[0] + lr0 * PITCH + lc0 * 16),
             A + (size_t)(row0 + lr0) * K + k0 + lc0 * 8, p0);
        cp16(s2u(smA[0] + lr1 * PITCH + lc1 * 16),
             A + (size_t)(row0 + lr1) * K + k0 + lc1 * 8, p1);
        cp16(s2u(smB[0] + lr0 * PITCH + lc0 * 16),
             Wb + (size_t)lr0 * ldw + k0 + lc0 * 8, true);
        cp16(s2u(smB[0] + lr1 * PITCH + lc1 * 16),
             Wb + (size_t)lr1 * ldw + k0 + lc1 * 8, true);
        CP_COMMIT();
    }

    for (int kt = 0; kt < NT; kt++) {
        if (kt + 1 < NT) {
            int k0 = (kt + 1) << 5;
            int nb = (kt + 1) & 1;
            cp16(s2u(smA[nb] + lr0 * PITCH + lc0 * 16),
                 A + (size_t)(row0 + lr0) * K + k0 + lc0 * 8, p0);
            cp16(s2u(smA[nb] + lr1 * PITCH + lc1 * 16),
                 A + (size_t)(row0 + lr1) * K + k0 + lc1 * 8, p1);
            cp16(s2u(smB[nb] + lr0 * PITCH + lc0 * 16),
                 Wb + (size_t)lr0 * ldw + k0 + lc0 * 8, true);
            cp16(s2u(smB[nb] + lr1 * PITCH + lc1 * 16),
                 Wb + (size_t)lr1 * ldw + k0 + lc1 * 8, true);
            CP_COMMIT();
            CP_WAIT1();
        } else {
            CP_WAIT0();
        }
        __syncthreads();

        const unsigned char* Ab = smA[kt & 1];
        const unsigned char* Bb = smB[kt & 1];
        #pragma unroll
        for (int ks = 0; ks < 2; ks++) {
            const int q0 = ks * 8 + (lane & 3);
            unsigned af[2][4];
            #pragma unroll
            for (int mi = 0; mi < 2; mi++) {
                int r = warpM * 32 + mi * 16 + (lane >> 2);
                af[mi][0] = *(const unsigned*)(Ab + r * PITCH + q0 * 4);
                af[mi][1] = *(const unsigned*)(Ab + (r + 8) * PITCH + q0 * 4);
                af[mi][2] = *(const unsigned*)(Ab + r * PITCH + (q0 + 4) * 4);
                af[mi][3] = *(const unsigned*)(Ab + (r + 8) * PITCH + (q0 + 4) * 4);
            }
            #pragma unroll
            for (int ni = 0; ni < 8; ni++) {
                int n = warpN * 64 + ni * 8 + (lane >> 2);
                unsigned b0 = *(const unsigned*)(Bb + n * PITCH + q0 * 4);
                unsigned b1 = *(const unsigned*)(Bb + n * PITCH + (q0 + 4) * 4);
                mma_bf16(acc[0][ni], af[0], b0, b1);
                mma_bf16(acc[1][ni], af[1], b0, b1);
            }
        }
        __syncthreads();
    }

    #pragma unroll
    for (int mi = 0; mi < 2; mi++) {
        int rbase = row0 + warpM * 32 + mi * 16 + (lane >> 2);
        #pragma unroll
        for (int ni = 0; ni < 8; ni++) {
            int col = warpN * 64 + ni * 8 + 2 * (lane & 3);
            if (blockIdx.y == 0) {
                if (rbase < NNODES)
                    *(float2*)(Cs + (size_t)rbase * NHID + col) =
                        make_float2(acc[mi][ni][0], acc[mi][ni][1]);
                if (rbase + 8 < NNODES)
                    *(float2*)(Cs + (size_t)(rbase + 8) * NHID + col) =
                        make_float2(acc[mi][ni][2], acc[mi][ni][3]);
            } else {
                if (rbase < NNODES)
                    *(__half2*)(Czh + (size_t)rbase * NHID + col) =
                        __floats2half2_rn(acc[mi][ni][0], acc[mi][ni][1]);
                if (rbase + 8 < NNODES)
                    *(__half2*)(Czh + (size_t)(rbase + 8) * NHID + col) =
                        __floats2half2_rn(acc[mi][ni][2], acc[mi][ni][3]);
            }
        }
    }
}

// ---------------- SpMM + epilogue: h = relu(s + (A@z)/(deg+1)) -> bf16 ----------------
__global__ __launch_bounds__(256) void k_spmm(const __half* __restrict__ zh,
                                              const float* __restrict__ s,
                                              const int* __restrict__ rp,
                                              const int* __restrict__ col,
                                              __nv_bfloat16* __restrict__ hb) {
    int lane = threadIdx.x & 31;
    int n    = (blockIdx.x * 256 + threadIdx.x) >> 5;
    if (n >= NNODES) return;
    int e = rp[n], end = rp[n + 1];
    int deg = end - e;
    float ax = 0.f, ay = 0.f, az = 0.f, aw = 0.f;
    for (; e + 2 <= end; e += 2) {
        int c0 = col[e], c1 = col[e + 1];
        uint2 u0 = *(const uint2*)(zh + (size_t)c0 * NHID + lane * 4);
        uint2 u1 = *(const uint2*)(zh + (size_t)c1 * NHID + lane * 4);
        float2 p0 = __half22float2(*(__half2*)&u0.x);
        float2 p1 = __half22float2(*(__half2*)&u0.y);
        float2 q0 = __half22float2(*(__half2*)&u1.x);
        float2 q1 = __half22float2(*(__half2*)&u1.y);
        ax += p0.x + q0.x; ay += p0.y + q0.y;
        az += p1.x + q1.x; aw += p1.y + q1.y;
    }
    if (e < end) {
        int c0 = col[e];
        uint2 u0 = *(const uint2*)(zh + (size_t)c0 * NHID + lane * 4);
        float2 p0 = __half22float2(*(__half2*)&u0.x);
        float2 p1 = __half22float2(*(__half2*)&u0.y);
        ax += p0.x; ay += p0.y; az += p1.x; aw += p1.y;
    }
    float inv = 1.0f / (1.0f + (float)deg);
    float4 sv = *(const float4*)(s + (size_t)n * NHID + lane * 4);
    float ox = fmaxf(fmaf(ax, inv, sv.x), 0.f);
    float oy = fmaxf(fmaf(ay, inv, sv.y), 0.f);
    float oz = fmaxf(fmaf(az, inv, sv.z), 0.f);
    float ow = fmaxf(fmaf(aw, inv, sv.w), 0.f);
    *(uint2*)(hb + (size_t)n * NHID + lane * 4) =
        make_uint2(pack_bf16x2(ox, oy), pack_bf16x2(oz, ow));
}

// ---------------- MLP + log_softmax (tf32 MMA; A from bf16 h) ----------------
__global__ __launch_bounds__(128) void k_mlp_tc(const __nv_bfloat16* __restrict__ hb,
                                                const float* __restrict__ Wm,
                                                const float* __restrict__ b,
                                                float* __restrict__ out) {
    __shared__ unsigned As[32][132];
    __shared__ unsigned Bsm[NCLASS][132];
    __shared__ float    Ls[128][41];
    __shared__ float    bs[NCLASS];

    const int tid = threadIdx.x, lane = tid & 31, wid = tid >> 5;
    const int row0 = blockIdx.x * 128;

    for (int i = tid; i < NCLASS * NHID; i += 128)
        Bsm[i >> 7][i & 127] = f2tf32(Wm[i]);
    if (tid < NCLASS) bs[tid] = b[tid];

    float acc[2][5][4];
    #pragma unroll
    for (int mi = 0; mi < 2; mi++)
        #pragma unroll
        for (int ni = 0; ni < 5; ni++)
            #pragma unroll
            for (int q = 0; q < 4; q++) acc[mi][ni][q] = 0.f;

    for (int k0 = 0; k0 < NHID; k0 += 32) {
        #pragma unroll
        for (int j = 0; j < 8; j++) {
            int i  = tid + j * 128;
            int r  = i >> 3;
            int c4 = (i & 7) * 4;
            uint2 u = make_uint2(0u, 0u);
            if (row0 + r < NNODES)
                u = *(const uint2*)(hb + (size_t)(row0 + r) * NHID + k0 + c4);
            // bf16 bits << 16 are valid tf32/fp32 operands
            As[c4 + 0][r] = u.x << 16;
            As[c4 + 1][r] = u.x & 0xffff0000u;
            As[c4 + 2][r] = u.y << 16;
            As[c4 + 3][r] = u.y & 0xffff0000u;
        }
        __syncthreads();

        #pragma unroll
        for (int kk = 0; kk < 32; kk += 8) {
            const int kc = kk + (lane & 3);
            unsigned af[2][4];
            #pragma unroll
            for (int mi = 0; mi < 2; mi++) {
                int r = wid * 32 + mi * 16 + (lane >> 2);
                af[mi][0] = As[kc][r];
                af[mi][1] = As[kc][r + 8];
                af[mi][2] = As[kc + 4][r];
                af[mi][3] = As[kc + 4][r + 8];
            }
            #pragma unroll
            for (int ni = 0; ni < 5; ni++) {
                int n = ni * 8 + (lane >> 2);
                unsigned b0 = Bsm[n][k0 + kc];
                unsigned b1 = Bsm[n][k0 + kc + 4];
                mma_tf32(acc[0][ni], af[0], b0, b1);
                mma_tf32(acc[1][ni], af[1], b0, b1);
            }
        }
        __syncthreads();
    }

    #pragma unroll
    for (int mi = 0; mi < 2; mi++) {
        int r = wid * 32 + mi * 16 + (lane >> 2);
        #pragma unroll
        for (int ni = 0; ni < 5; ni++) {
            int c = ni * 8 + 2 * (lane & 3);
            Ls[r][c]         = acc[mi][ni][0];
            Ls[r][c + 1]     = acc[mi][ni][1];
            Ls[r + 8][c]     = acc[mi][ni][2];
            Ls[r + 8][c + 1] = acc[mi][ni][3];
        }
    }
    __syncthreads();

    int gr = row0 + tid;
    if (gr >= NNODES) return;
    float l[NCLASS];
    float m = -INFINITY;
    #pragma unroll
    for (int c = 0; c < NCLASS; c++) {
        l[c] = Ls[tid][c] + bs[c];
        m = fmaxf(m, l[c]);
    }
    float se = 0.f;
    #pragma unroll
    for (int c = 0; c < NCLASS; c++) se += expf(l[c] - m);
    float lse = m + logf(se);
    float* op = out + (size_t)gr * NCLASS;
    #pragma unroll
    for (int c = 0; c < NCLASS; c += 4)
        *(float4*)(op + c) = make_float4(l[c] - lse, l[c + 1] - lse,
                                         l[c + 2] - lse, l[c + 3] - lse);
}

// ---------------- launch ----------------
extern "C" void kernel_launch(void* const* d_in, const int* in_sizes, int n_in,
                              void* d_out, int out_size) {
    const float* x    = (const float*)d_in[0];
    const float* W1   = (const float*)d_in[1];   // [128, 512]
    const float* W2   = (const float*)d_in[2];   // [128, 256]
    const float* mW   = (const float*)d_in[3];   // [40, 128]
    const float* mb   = (const float*)d_in[4];   // [40]
    const int*   rows = (const int*)d_in[5];
    const int*   cols = (const int*)d_in[6];
    float*       out  = (float*)d_out;

    float* p_s;
    __half* p_zh;
    __nv_bfloat16 *p_hb, *p_xb, *p_w1b, *p_w2b;
    int *p_deg, *p_rp, *p_cur, *p_col;
    cudaGetSymbolAddress((void**)&p_s,   g_s);
    cudaGetSymbolAddress((void**)&p_zh,  g_zh);
    cudaGetSymbolAddress((void**)&p_hb,  g_hb);
    cudaGetSymbolAddress((void**)&p_xb,  g_xb);
    cudaGetSymbolAddress((void**)&p_w1b, g_w1b);
    cudaGetSymbolAddress((void**)&p_w2b, g_w2b);
    cudaGetSymbolAddress((void**)&p_deg, g_deg);
    cudaGetSymbolAddress((void**)&p_rp,  g_rowptr);
    cudaGetSymbolAddress((void**)&p_cur, g_cursor);
    cudaGetSymbolAddress((void**)&p_col, g_col);

    const int GB_E = (NEDGES + 255) / 256;
    const int GB_W = (NNODES * 32 + 255) / 256;
    const int GB_T = (NNODES + 127) / 128;
    const dim3 GB_G(GB_T, 2);

    // bf16 conversions (per replay)
    int n4x  = NNODES * NFEAT / 4;
    int n4w1 = NHID * 2 * NFEAT / 4;
    int n4w2 = NHID * 2 * NHID / 4;
    k_cvt<<<(n4x + 255) / 256, 256>>>(x,  p_xb,  n4x);
    k_cvt<<<(n4w1 + 255) / 256, 256>>>(W1, p_w1b, n4w1);
    k_cvt<<<(n4w2 + 255) / 256, 256>>>(W2, p_w2b, n4w2);

    // CSR build (per replay)
    cudaMemsetAsync(p_deg, 0, NNODES * sizeof(int));
    k_count<<<GB_E, 256>>>(rows, p_deg);
    k_scan<<<1, 1024>>>(p_deg, p_rp, p_cur);
    k_fill<<<GB_E, 256>>>(rows, cols, p_cur, p_col);

    // Layer 1
    k_gemm_bf16<<<GB_G, 256>>>(p_xb, NFEAT, p_w1b, p_s, p_zh);
    k_spmm<<<GB_W, 256>>>(p_zh, p_s, p_rp, p_col, p_hb);

    // Layer 2
    k_gemm_bf16<<<GB_G, 256>>>(p_hb, NHID, p_w2b, p_s, p_zh);
    k_spmm<<<GB_W, 256>>>(p_zh, p_s, p_rp, p_col, p_hb);

    // MLP + log_softmax
    k_mlp_tc<<<GB_T, 128>>>(p_hb, mW, mb, out);
}

// round 8
// speedup vs baseline: 3.0151x; 1.1700x over previous
#include <cuda_runtime.h>
#include <cuda_fp16.h>
#include <cuda_bf16.h>
#include <math.h>

#define NNODES 100000
#define NEDGES 3200000
#define NFEAT  256
#define NHID   128
#define NCLASS 40

// ---------------- scratch (static device globals; no allocs) ----------------
__device__ float          g_s[(size_t)NNODES * NHID];    // self-projection fp32
__device__ __half         g_zh[(size_t)NNODES * NHID];   // neighbor proj fp16
__device__ __nv_bfloat16  g_hb[(size_t)NNODES * NHID];   // layer output bf16
__device__ __nv_bfloat16  g_xb[(size_t)NNODES * NFEAT];  // x in bf16
__device__ __nv_bfloat16  g_w1b[NHID * 2 * NFEAT];
__device__ __nv_bfloat16  g_w2b[NHID * 2 * NHID];
__device__ int            g_deg[NNODES];
__device__ int            g_rowptr[NNODES + 1];
__device__ int            g_cursor[NNODES];
__device__ int            g_col[NEDGES];

// ---------------- helpers ----------------
__device__ __forceinline__ unsigned pack_bf16x2(float lo, float hi) {
    unsigned u;
    asm("cvt.rn.bf16x2.f32 %0, %1, %2;" : "=r"(u) : "f"(hi), "f"(lo));
    return u;
}
__device__ __forceinline__ unsigned f2tf32(float v) {
    unsigned u;
    asm("cvt.rna.tf32.f32 %0, %1;" : "=r"(u) : "f"(v));
    return u;
}
__device__ __forceinline__ void mma_bf16(float* c, const unsigned* a,
                                         unsigned b0, unsigned b1) {
    asm volatile(
        "mma.sync.aligned.m16n8k16.row.col.f32.bf16.bf16.f32 "
        "{%0,%1,%2,%3}, {%4,%5,%6,%7}, {%8,%9}, {%0,%1,%2,%3};"
        : "+f"(c[0]), "+f"(c[1]), "+f"(c[2]), "+f"(c[3])
        : "r"(a[0]), "r"(a[1]), "r"(a[2]), "r"(a[3]), "r"(b0), "r"(b1));
}
__device__ __forceinline__ void mma_tf32(float* c, const unsigned* a,
                                         unsigned b0, unsigned b1) {
    asm volatile(
        "mma.sync.aligned.m16n8k8.row.col.f32.tf32.tf32.f32 "
        "{%0,%1,%2,%3}, {%4,%5,%6,%7}, {%8,%9}, {%0,%1,%2,%3};"
        : "+f"(c[0]), "+f"(c[1]), "+f"(c[2]), "+f"(c[3])
        : "r"(a[0]), "r"(a[1]), "r"(a[2]), "r"(a[3]), "r"(b0), "r"(b1));
}
__device__ __forceinline__ unsigned s2u(const void* p) {
    return (unsigned)__cvta_generic_to_shared(p);
}
__device__ __forceinline__ void cp16(unsigned dst, const void* src, bool pred) {
    int sz = pred ? 16 : 0;
    asm volatile("cp.async.cg.shared.global [%0], [%1], 16, %2;"
                 :: "r"(dst), "l"(src), "r"(sz));
}
#define CP_COMMIT() asm volatile("cp.async.commit_group;")
#define CP_WAIT1()  asm volatile("cp.async.wait_group 1;")
#define CP_WAIT0()  asm volatile("cp.async.wait_group 0;")

// ---------------- fp32 -> bf16 convert ----------------
__global__ void k_cvt(const float* __restrict__ in, __nv_bfloat16* __restrict__ out,
                      int n4) {
    int i = blockIdx.x * blockDim.x + threadIdx.x;
    if (i < n4) {
        float4 v = ((const float4*)in)[i];
        ((uint2*)out)[i] = make_uint2(pack_bf16x2(v.x, v.y), pack_bf16x2(v.z, v.w));
    }
}

// ---------------- CSR build (4 edges / thread) ----------------
__global__ void k_count(const int* __restrict__ rows, int* __restrict__ deg) {
    int i = blockIdx.x * blockDim.x + threadIdx.x;
    if (i < NEDGES / 4) {
        int4 r = ((const int4*)rows)[i];
        atomicAdd(&deg[r.x], 1);
        atomicAdd(&deg[r.y], 1);
        atomicAdd(&deg[r.z], 1);
        atomicAdd(&deg[r.w], 1);
    }
}

__global__ void k_scan(const int* __restrict__ deg, int* __restrict__ rp,
                       int* __restrict__ cur) {
    __shared__ int wsum[32];
    __shared__ int carry;
    int tid = threadIdx.x, lane = tid & 31, wid = tid >> 5;
    if (tid == 0) carry = 0;
    __syncthreads();
    for (int base = 0; base < NNODES; base += 1024) {
        int i = base + tid;
        int v = (i < NNODES) ? deg[i] : 0;
        int x = v;
        #pragma unroll
        for (int d = 1; d < 32; d <<= 1) {
            int y = __shfl_up_sync(0xffffffffu, x, d);
            if (lane >= d) x += y;
        }
        if (lane == 31) wsum[wid] = x;
        __syncthreads();
        if (wid == 0) {
            int s = wsum[lane];
            #pragma unroll
            for (int d = 1; d < 32; d <<= 1) {
                int y = __shfl_up_sync(0xffffffffu, s, d);
                if (lane >= d) s += y;
            }
            wsum[lane] = s;
        }
        __syncthreads();
        int off  = carry + (wid ? wsum[wid - 1] : 0);
        int excl = off + x - v;
        if (i < NNODES) { rp[i] = excl; cur[i] = excl; }
        int tot = wsum[31];
        __syncthreads();
        if (tid == 0) carry += tot;
        __syncthreads();
    }
    if (tid == 0) rp[NNODES] = carry;
}

__global__ void k_fill(const int* __restrict__ rows, const int* __restrict__ cols,
                       int* __restrict__ cur, int* __restrict__ col) {
    int i = blockIdx.x * blockDim.x + threadIdx.x;
    if (i < NEDGES / 4) {
        int4 r = ((const int4*)rows)[i];
        int4 c = ((const int4*)cols)[i];
        col[atomicAdd(&cur[r.x], 1)] = c.x;
        col[atomicAdd(&cur[r.y], 1)] = c.y;
        col[atomicAdd(&cur[r.z], 1)] = c.z;
        col[atomicAdd(&cur[r.w], 1)] = c.w;
    }
}

// ---------------- pipelined bf16 GEMM ----------------
#define PITCH 80
__global__ __launch_bounds__(256) void k_gemm_bf16(
    const __nv_bfloat16* __restrict__ A, int K,
    const __nv_bfloat16* __restrict__ W,
    float* __restrict__ Cs, __half* __restrict__ Czh)
{
    __shared__ __align__(16) unsigned char smA[2][128 * PITCH];
    __shared__ __align__(16) unsigned char smB[2][128 * PITCH];
    const int tid = threadIdx.x, lane = tid & 31, wid = tid >> 5;
    const int warpM = wid & 3, warpN = wid >> 2;
    const int row0 = blockIdx.x * 128;
    const int ldw = 2 * K;
    const __nv_bfloat16* Wb = W + (size_t)blockIdx.y * K;
    const int NT = K >> 5;

    const int lr0 = tid >> 2, lc0 = tid & 3;
    const int lr1 = (tid + 256) >> 2, lc1 = lc0;
    const bool p0 = (row0 + lr0) < NNODES;
    const bool p1 = (row0 + lr1) < NNODES;

    float acc[2][8][4];
    #pragma unroll
    for (int mi = 0; mi < 2; mi++)
        #pragma unroll
        for (int ni = 0; ni < 8; ni++)
            #pragma unroll
            for (int q = 0; q < 4; q++) acc[mi][ni][q] = 0.f;

    {
        cp16(s2u(smA[0] + lr0 * PITCH + lc0 * 16),
             A + (size_t)(row0 + lr0) * K + lc0 * 8, p0);
        cp16(s2u(smA[0] + lr1 * PITCH + lc1 * 16),
             A + (size_t)(row0 + lr1) * K + lc1 * 8, p1);
        cp16(s2u(smB[0] + lr0 * PITCH + lc0 * 16),
             Wb + (size_t)lr0 * ldw + lc0 * 8, true);
        cp16(s2u(smB[0] + lr1 * PITCH + lc1 * 16),
             Wb + (size_t)lr1 * ldw + lc1 * 8, true);
        CP_COMMIT();
    }

    for (int kt = 0; kt < NT; kt++) {
        if (kt + 1 < NT) {
            int k0 = (kt + 1) << 5;
            int nb = (kt + 1) & 1;
            cp16(s2u(smA[nb] + lr0 * PITCH + lc0 * 16),
                 A + (size_t)(row0 + lr0) * K + k0 + lc0 * 8, p0);
            cp16(s2u(smA[nb] + lr1 * PITCH + lc1 * 16),
                 A + (size_t)(row0 + lr1) * K + k0 + lc1 * 8, p1);
            cp16(s2u(smB[nb] + lr0 * PITCH + lc0 * 16),
                 Wb + (size_t)lr0 * ldw + k0 + lc0 * 8, true);
            cp16(s2u(smB[nb] + lr1 * PITCH + lc1 * 16),
                 Wb + (size_t)lr1 * ldw + k0 + lc1 * 8, true);
            CP_COMMIT();
            CP_WAIT1();
        } else {
            CP_WAIT0();
        }
        __syncthreads();

        const unsigned char* Ab = smA[kt & 1];
        const unsigned char* Bb = smB[kt & 1];
        #pragma unroll
        for (int ks = 0; ks < 2; ks++) {
            const int q0 = ks * 8 + (lane & 3);
            unsigned af[2][4];
            #pragma unroll
            for (int mi = 0; mi < 2; mi++) {
                int r = warpM * 32 + mi * 16 + (lane >> 2);
                af[mi][0] = *(const unsigned*)(Ab + r * PITCH + q0 * 4);
                af[mi][1] = *(const unsigned*)(Ab + (r + 8) * PITCH + q0 * 4);
                af[mi][2] = *(const unsigned*)(Ab + r * PITCH + (q0 + 4) * 4);
                af[mi][3] = *(const unsigned*)(Ab + (r + 8) * PITCH + (q0 + 4) * 4);
            }
            #pragma unroll
            for (int ni = 0; ni < 8; ni++) {
                int n = warpN * 64 + ni * 8 + (lane >> 2);
                unsigned b0 = *(const unsigned*)(Bb + n * PITCH + q0 * 4);
                unsigned b1 = *(const unsigned*)(Bb + n * PITCH + (q0 + 4) * 4);
                mma_bf16(acc[0][ni], af[0], b0, b1);
                mma_bf16(acc[1][ni], af[1], b0, b1);
            }
        }
        __syncthreads();
    }

    #pragma unroll
    for (int mi = 0; mi < 2; mi++) {
        int rbase = row0 + warpM * 32 + mi * 16 + (lane >> 2);
        #pragma unroll
        for (int ni = 0; ni < 8; ni++) {
            int col = warpN * 64 + ni * 8 + 2 * (lane & 3);
            if (blockIdx.y == 0) {
                if (rbase < NNODES)
                    *(float2*)(Cs + (size_t)rbase * NHID + col) =
                        make_float2(acc[mi][ni][0], acc[mi][ni][1]);
                if (rbase + 8 < NNODES)
                    *(float2*)(Cs + (size_t)(rbase + 8) * NHID + col) =
                        make_float2(acc[mi][ni][2], acc[mi][ni][3]);
            } else {
                if (rbase < NNODES)
                    *(__half2*)(Czh + (size_t)rbase * NHID + col) =
                        __floats2half2_rn(acc[mi][ni][0], acc[mi][ni][1]);
                if (rbase + 8 < NNODES)
                    *(__half2*)(Czh + (size_t)(rbase + 8) * NHID + col) =
                        __floats2half2_rn(acc[mi][ni][2], acc[mi][ni][3]);
            }
        }
    }
}

// ---------------- SpMM + epilogue: h = relu(s + (A@z)/(deg+1)) -> bf16 ----------------
__global__ __launch_bounds__(256) void k_spmm(const __half* __restrict__ zh,
                                              const float* __restrict__ s,
                                              const int* __restrict__ rp,
                                              const int* __restrict__ col,
                                              __nv_bfloat16* __restrict__ hb) {
    int lane = threadIdx.x & 31;
    int n    = (blockIdx.x * 256 + threadIdx.x) >> 5;
    if (n >= NNODES) return;
    int e = rp[n], end = rp[n + 1];
    int deg = end - e;
    float ax = 0.f, ay = 0.f, az = 0.f, aw = 0.f;
    for (; e + 2 <= end; e += 2) {
        int c0 = col[e], c1 = col[e + 1];
        uint2 u0 = *(const uint2*)(zh + (size_t)c0 * NHID + lane * 4);
        uint2 u1 = *(const uint2*)(zh + (size_t)c1 * NHID + lane * 4);
        float2 p0 = __half22float2(*(__half2*)&u0.x);
        float2 p1 = __half22float2(*(__half2*)&u0.y);
        float2 q0 = __half22float2(*(__half2*)&u1.x);
        float2 q1 = __half22float2(*(__half2*)&u1.y);
        ax += p0.x + q0.x; ay += p0.y + q0.y;
        az += p1.x + q1.x; aw += p1.y + q1.y;
    }
    if (e < end) {
        int c0 = col[e];
        uint2 u0 = *(const uint2*)(zh + (size_t)c0 * NHID + lane * 4);
        float2 p0 = __half22float2(*(__half2*)&u0.x);
        float2 p1 = __half22float2(*(__half2*)&u0.y);
        ax += p0.x; ay += p0.y; az += p1.x; aw += p1.y;
    }
    float inv = 1.0f / (1.0f + (float)deg);
    float4 sv = *(const float4*)(s + (size_t)n * NHID + lane * 4);
    float ox = fmaxf(fmaf(ax, inv, sv.x), 0.f);
    float oy = fmaxf(fmaf(ay, inv, sv.y), 0.f);
    float oz = fmaxf(fmaf(az, inv, sv.z), 0.f);
    float ow = fmaxf(fmaf(aw, inv, sv.w), 0.f);
    *(uint2*)(hb + (size_t)n * NHID + lane * 4) =
        make_uint2(pack_bf16x2(ox, oy), pack_bf16x2(oz, ow));
}

// ---------------- MLP + log_softmax (tf32 MMA; A from bf16 h) ----------------
__global__ __launch_bounds__(128) void k_mlp_tc(const __nv_bfloat16* __restrict__ hb,
                                                const float* __restrict__ Wm,
                                                const float* __restrict__ b,
                                                float* __restrict__ out) {
    __shared__ unsigned As[32][132];
    __shared__ unsigned Bsm[NCLASS][132];
    __shared__ float    Ls[128][41];
    __shared__ float    bs[NCLASS];

    const int tid = threadIdx.x, lane = tid & 31, wid = tid >> 5;
    const int row0 = blockIdx.x * 128;

    for (int i = tid; i < NCLASS * NHID; i += 128)
        Bsm[i >> 7][i & 127] = f2tf32(Wm[i]);
    if (tid < NCLASS) bs[tid] = b[tid];

    float acc[2][5][4];
    #pragma unroll
    for (int mi = 0; mi < 2; mi++)
        #pragma unroll
        for (int ni = 0; ni < 5; ni++)
            #pragma unroll
            for (int q = 0; q < 4; q++) acc[mi][ni][q] = 0.f;

    for (int k0 = 0; k0 < NHID; k0 += 32) {
        #pragma unroll
        for (int j = 0; j < 8; j++) {
            int i  = tid + j * 128;
            int r  = i >> 3;
            int c4 = (i & 7) * 4;
            uint2 u = make_uint2(0u, 0u);
            if (row0 + r < NNODES)
                u = *(const uint2*)(hb + (size_t)(row0 + r) * NHID + k0 + c4);
            As[c4 + 0][r] = u.x << 16;
            As[c4 + 1][r] = u.x & 0xffff0000u;
            As[c4 + 2][r] = u.y << 16;
            As[c4 + 3][r] = u.y & 0xffff0000u;
        }
        __syncthreads();

        #pragma unroll
        for (int kk = 0; kk < 32; kk += 8) {
            const int kc = kk + (lane & 3);
            unsigned af[2][4];
            #pragma unroll
            for (int mi = 0; mi < 2; mi++) {
                int r = wid * 32 + mi * 16 + (lane >> 2);
                af[mi][0] = As[kc][r];
                af[mi][1] = As[kc][r + 8];
                af[mi][2] = As[kc + 4][r];
                af[mi][3] = As[kc + 4][r + 8];
            }
            #pragma unroll
            for (int ni = 0; ni < 5; ni++) {
                int n = ni * 8 + (lane >> 2);
                unsigned b0 = Bsm[n][k0 + kc];
                unsigned b1 = Bsm[n][k0 + kc + 4];
                mma_tf32(acc[0][ni], af[0], b0, b1);
                mma_tf32(acc[1][ni], af[1], b0, b1);
            }
        }
        __syncthreads();
    }

    #pragma unroll
    for (int mi = 0; mi < 2; mi++) {
        int r = wid * 32 + mi * 16 + (lane >> 2);
        #pragma unroll
        for (int ni = 0; ni < 5; ni++) {
            int c = ni * 8 + 2 * (lane & 3);
            Ls[r][c]         = acc[mi][ni][0];
            Ls[r][c + 1]     = acc[mi][ni][1];
            Ls[r + 8][c]     = acc[mi][ni][2];
            Ls[r + 8][c + 1] = acc[mi][ni][3];
        }
    }
    __syncthreads();

    int gr = row0 + tid;
    if (gr >= NNODES) return;
    float l[NCLASS];
    float m = -INFINITY;
    #pragma unroll
    for (int c = 0; c < NCLASS; c++) {
        l[c] = Ls[tid][c] + bs[c];
        m = fmaxf(m, l[c]);
    }
    float se = 0.f;
    #pragma unroll
    for (int c = 0; c < NCLASS; c++) se += expf(l[c] - m);
    float lse = m + logf(se);
    float* op = out + (size_t)gr * NCLASS;
    #pragma unroll
    for (int c = 0; c < NCLASS; c += 4)
        *(float4*)(op + c) = make_float4(l[c] - lse, l[c + 1] - lse,
                                         l[c + 2] - lse, l[c + 3] - lse);
}

// ---------------- launch ----------------
extern "C" void kernel_launch(void* const* d_in, const int* in_sizes, int n_in,
                              void* d_out, int out_size) {
    const float* x    = (const float*)d_in[0];
    const float* W1   = (const float*)d_in[1];   // [128, 512]
    const float* W2   = (const float*)d_in[2];   // [128, 256]
    const float* mW   = (const float*)d_in[3];   // [40, 128]
    const float* mb   = (const float*)d_in[4];   // [40]
    const int*   rows = (const int*)d_in[5];
    const int*   cols = (const int*)d_in[6];
    float*       out  = (float*)d_out;

    float* p_s;
    __half* p_zh;
    __nv_bfloat16 *p_hb, *p_xb, *p_w1b, *p_w2b;
    int *p_deg, *p_rp, *p_cur, *p_col;
    cudaGetSymbolAddress((void**)&p_s,   g_s);
    cudaGetSymbolAddress((void**)&p_zh,  g_zh);
    cudaGetSymbolAddress((void**)&p_hb,  g_hb);
    cudaGetSymbolAddress((void**)&p_xb,  g_xb);
    cudaGetSymbolAddress((void**)&p_w1b, g_w1b);
    cudaGetSymbolAddress((void**)&p_w2b, g_w2b);
    cudaGetSymbolAddress((void**)&p_deg, g_deg);
    cudaGetSymbolAddress((void**)&p_rp,  g_rowptr);
    cudaGetSymbolAddress((void**)&p_cur, g_cursor);
    cudaGetSymbolAddress((void**)&p_col, g_col);

    // host-side handles only (no device memory) — created once
    static cudaStream_t s_side = nullptr;
    static cudaEvent_t  ev_fork = nullptr, ev_join = nullptr;
    if (s_side == nullptr) {
        cudaStreamCreate(&s_side);
        cudaEventCreateWithFlags(&ev_fork, cudaEventDisableTiming);
        cudaEventCreateWithFlags(&ev_join, cudaEventDisableTiming);
    }

    const int GB_E4 = (NEDGES / 4 + 255) / 256;
    const int GB_W  = (NNODES * 32 + 255) / 256;
    const int GB_T  = (NNODES + 127) / 128;
    const dim3 GB_G(GB_T, 2);

    // ---- fork: CSR build on side stream, concurrent with cvt + GEMM1 ----
    cudaEventRecord(ev_fork, 0);
    cudaStreamWaitEvent(s_side, ev_fork, 0);

    cudaMemsetAsync(p_deg, 0, NNODES * sizeof(int), s_side);
    k_count<<<GB_E4, 256, 0, s_side>>>(rows, p_deg);
    k_scan<<<1, 1024, 0, s_side>>>(p_deg, p_rp, p_cur);
    k_fill<<<GB_E4, 256, 0, s_side>>>(rows, cols, p_cur, p_col);
    cudaEventRecord(ev_join, s_side);

    // ---- main stream: bf16 conversions + layer-1 GEMM ----
    int n4x  = NNODES * NFEAT / 4;
    int n4w1 = NHID * 2 * NFEAT / 4;
    int n4w2 = NHID * 2 * NHID / 4;
    k_cvt<<<(n4w1 + 255) / 256, 256>>>(W1, p_w1b, n4w1);
    k_cvt<<<(n4w2 + 255) / 256, 256>>>(W2, p_w2b, n4w2);
    k_cvt<<<(n4x + 255) / 256, 256>>>(x,  p_xb,  n4x);
    k_gemm_bf16<<<GB_G, 256>>>(p_xb, NFEAT, p_w1b, p_s, p_zh);

    // ---- join: SpMM needs CSR + z + s ----
    cudaStreamWaitEvent(0, ev_join, 0);
    k_spmm<<<GB_W, 256>>>(p_zh, p_s, p_rp, p_col, p_hb);

    // Layer 2
    k_gemm_bf16<<<GB_G, 256>>>(p_hb, NHID, p_w2b, p_s, p_zh);
    k_spmm<<<GB_W, 256>>>(p_zh, p_s, p_rp, p_col, p_hb);

    // MLP + log_softmax
    k_mlp_tc<<<GB_T, 128>>>(p_hb, mW, mb, out);
}